// round 13
// baseline (speedup 1.0000x reference)
#include <cuda_runtime.h>
#include <cuda_bf16.h>
#include <cuda_fp16.h>
#include <math.h>
#include <stdint.h>

#define NNODES 100000
#define NEDGES 1600000
#define NPAD   100096          // 391 clusters * 256 rows
#define NCTAS  782
#define SCAN_BLOCKS 391        // ceil(NNODES/256)

// Arch-specific guard: tcgen05 only exists in the sm_103a / family-specific pass.
#ifndef __CUDA_ARCH_FAMILY_SPECIFIC__
#define __CUDA_ARCH_FAMILY_SPECIFIC__ 0
#endif
#ifndef __CUDA_ARCH_SPECIFIC__
#define __CUDA_ARCH_SPECIFIC__ 0
#endif
#if defined(__CUDA_ARCH__) && (defined(__CUDA_ARCH_FEAT_SM103_ALL) || \
    (__CUDA_ARCH_FAMILY_SPECIFIC__ == 1030) || (__CUDA_ARCH_SPECIFIC__ == 1030))
#define TC_OK 1
#else
#define TC_OK 0
#endif

// ---------------- device scratch (static, no allocation) ----------------
__device__ float g_dis[NNODES];
__device__ int   g_cnt[NNODES];
__device__ int   g_loc[NNODES];
__device__ int   g_bsum[512];
__device__ int   g_cur[NNODES];
__device__ int2  g_rec[NEDGES];                      // packed {src, norm-as-int}
__device__ __half g_xh[(size_t)NNODES * 256];        // fp16 [x row | h row], 512B/node
__device__ __nv_bfloat16 g_Ah[(size_t)NPAD * 512];   // [x|Lx|h|Lh] hi
__device__ __nv_bfloat16 g_Al[(size_t)NPAD * 512];   // lo residual (x/h cols only)
__device__ __nv_bfloat16 g_Wth[512 * 512];           // W^T hi  [outcol][k]
__device__ __nv_bfloat16 g_Wtl[512 * 512];           // W^T lo
__device__ float g_bias[512];
__device__ int   g_idx64;

__device__ __forceinline__ int get_idx(const void* ei, long long pos) {
    if (g_idx64) return (int)((const long long*)ei)[pos];
    return ((const int*)ei)[pos];
}

// streaming (evict-first) 8B / 16B stores
__device__ __forceinline__ void stcs8(void* p, uint2 v) {
    unsigned long long u = (unsigned long long)v.x | ((unsigned long long)v.y << 32);
    asm volatile("st.global.cs.b64 [%0], %1;" :: "l"(p), "l"(u) : "memory");
}
__device__ __forceinline__ void stcs16(void* p, float4 v) {
    asm volatile("st.global.cs.v4.f32 [%0], {%1,%2,%3,%4};"
                 :: "l"(p), "f"(v.x), "f"(v.y), "f"(v.z), "f"(v.w) : "memory");
}

// ------- zero accumulators + edge dtype detection + fp16 [x|h] row packing -------
__global__ void prep_k(const void* ei, const float* __restrict__ x,
                       const float* __restrict__ hprev) {
    int tid = threadIdx.x;
    int i = blockIdx.x * 256 + tid;
    if (i < NNODES) { g_dis[i] = 0.f; g_cnt[i] = 0; g_cur[i] = 0; }
    if (blockIdx.x == 0 && tid == 0) {
        const unsigned long long* p = (const unsigned long long*)ei;
        int ok64 = 1;
        for (int k = 0; k < 256; k++)
            if (p[k] >= (unsigned long long)NNODES) { ok64 = 0; break; }
        g_idx64 = ok64;
    }
    int node = blockIdx.x * 8 + (tid >> 5);
    int lane = tid & 31;
    if (node < NNODES) {
        float4 vx = ((const float4*)(x + (size_t)node * 128))[lane];
        float4 vh = ((const float4*)(hprev + (size_t)node * 128))[lane];
        __half2 x01 = __floats2half2_rn(vx.x, vx.y);
        __half2 x23 = __floats2half2_rn(vx.z, vx.w);
        __half2 h01 = __floats2half2_rn(vh.x, vh.y);
        __half2 h23 = __floats2half2_rn(vh.z, vh.w);
        uint2 px, ph;
        px.x = *(unsigned*)&x01; px.y = *(unsigned*)&x23;
        ph.x = *(unsigned*)&h01; ph.y = *(unsigned*)&h23;
        ((uint2*)g_xh)[(size_t)node * 64 + lane] = px;        // x: bytes 0..255
        ((uint2*)g_xh)[(size_t)node * 64 + 32 + lane] = ph;   // h: bytes 256..511
    }
}

// ---------------- pack W^T in bf16 hi/lo + bias ----------------
__global__ void buildw_k(const float* __restrict__ Wx0, const float* __restrict__ Wx1,
                         const float* __restrict__ Wh0, const float* __restrict__ Wh1,
                         const float* __restrict__ bx,  const float* __restrict__ bh) {
    int idx = blockIdx.x * blockDim.x + threadIdx.x;
    if (idx >= 512 * 512) return;
    int c = idx >> 9;        // k index
    int j = idx & 511;       // output col
    int g = j >> 7;
    int h = j & 127;
    int part = c >> 7;
    int cc = c & 127;
    const float* W = (part == 0) ? Wx0 : (part == 1) ? Wx1 : (part == 2) ? Wh0 : Wh1;
    float wv = W[((size_t)g * 128 + cc) * 128 + h];
    __nv_bfloat16 hi = __float2bfloat16(wv);
    float lo = wv - __bfloat162float(hi);
    g_Wth[(size_t)j * 512 + c] = hi;
    g_Wtl[(size_t)j * 512 + c] = __float2bfloat16(lo);
    if (c == 0) g_bias[j] = bx[g * 128 + h] + bh[g * 128 + h];
}

// ------- degree (sum w over src) + in-degree count (dst), 4 edges/thread -------
__global__ void deg_k(const void* __restrict__ ei, const float* __restrict__ w) {
    int e0 = (blockIdx.x * blockDim.x + threadIdx.x) * 4;
    if (e0 >= NEDGES) return;                 // NEDGES % 4 == 0
    int s[4], d[4];
    float ww[4];
#pragma unroll
    for (int i = 0; i < 4; i++) {
        s[i] = get_idx(ei, e0 + i);
        d[i] = get_idx(ei, (long long)NEDGES + e0 + i);
        ww[i] = w[e0 + i];
    }
#pragma unroll
    for (int i = 0; i < 4; i++) {
        atomicAdd(&g_dis[s[i]], ww[i]);
        atomicAdd(&g_cnt[d[i]], 1);
    }
}

// -------- scan pass 1 (per-block exclusive scan of g_cnt) + fused deg^{-1/2} --------
__global__ void scan1_k() {
    __shared__ int s[256];
    int tid = threadIdx.x;
    int i = blockIdx.x * 256 + tid;
    if (i < NNODES) {
        float d = g_dis[i];
        g_dis[i] = (d > 0.f) ? rsqrtf(d) : 0.f;
    }
    int v = (i < NNODES) ? g_cnt[i] : 0;
    s[tid] = v;
    __syncthreads();
#pragma unroll
    for (int o = 1; o < 256; o <<= 1) {
        int t = (tid >= o) ? s[tid - o] : 0;
        __syncthreads();
        s[tid] += t;
        __syncthreads();
    }
    if (i < NNODES) g_loc[i] = s[tid] - v;
    if (tid == 255) g_bsum[blockIdx.x] = s[255];
}
__global__ void scan2_k() {
    __shared__ int s[512];
    int tid = threadIdx.x;
    int v = (tid < SCAN_BLOCKS) ? g_bsum[tid] : 0;
    s[tid] = v;
    __syncthreads();
#pragma unroll
    for (int o = 1; o < 512; o <<= 1) {
        int t = (tid >= o) ? s[tid - o] : 0;
        __syncthreads();
        s[tid] += t;
        __syncthreads();
    }
    if (tid < SCAN_BLOCKS) g_bsum[tid] = s[tid] - v;
}
__device__ __forceinline__ int csr_off(int node) {
    return g_bsum[node >> 8] + g_loc[node];
}

// ------- fill packed CSR records {src, norm} grouped by dst, 4 edges/thread -------
__global__ void fill_k(const void* __restrict__ ei, const float* __restrict__ w) {
    int e0 = (blockIdx.x * blockDim.x + threadIdx.x) * 4;
    if (e0 >= NEDGES) return;
    int s[4], d[4];
    float ww[4];
#pragma unroll
    for (int i = 0; i < 4; i++) {
        s[i] = get_idx(ei, e0 + i);
        d[i] = get_idx(ei, (long long)NEDGES + e0 + i);
        ww[i] = w[e0 + i];
    }
    float dis_s[4], dis_d[4];
#pragma unroll
    for (int i = 0; i < 4; i++) { dis_s[i] = g_dis[s[i]]; dis_d[i] = g_dis[d[i]]; }
#pragma unroll
    for (int i = 0; i < 4; i++) {
        float nm = -(dis_s[i] * ww[i] * dis_d[i]);
        int pos = csr_off(d[i]) + atomicAdd(&g_cur[d[i]], 1);
        g_rec[pos] = make_int2(s[i], __float_as_int(nm));
    }
}

// ---------------- bf16 hi/lo pack helpers ----------------
__device__ __forceinline__ uint2 pack_hilo(float4 v, uint2* lo) {
    __nv_bfloat16 h0 = __float2bfloat16(v.x), h1 = __float2bfloat16(v.y);
    __nv_bfloat16 h2 = __float2bfloat16(v.z), h3 = __float2bfloat16(v.w);
    __nv_bfloat16 l0 = __float2bfloat16(v.x - __bfloat162float(h0));
    __nv_bfloat16 l1 = __float2bfloat16(v.y - __bfloat162float(h1));
    __nv_bfloat16 l2 = __float2bfloat16(v.z - __bfloat162float(h2));
    __nv_bfloat16 l3 = __float2bfloat16(v.w - __bfloat162float(h3));
    uint2 ph;
    ph.x = (unsigned)__bfloat16_as_ushort(h0) | ((unsigned)__bfloat16_as_ushort(h1) << 16);
    ph.y = (unsigned)__bfloat16_as_ushort(h2) | ((unsigned)__bfloat16_as_ushort(h3) << 16);
    lo->x = (unsigned)__bfloat16_as_ushort(l0) | ((unsigned)__bfloat16_as_ushort(l1) << 16);
    lo->y = (unsigned)__bfloat16_as_ushort(l2) | ((unsigned)__bfloat16_as_ushort(l3) << 16);
    return ph;
}
__device__ __forceinline__ uint2 pack_hi_only(float4 v) {
    __nv_bfloat16 h0 = __float2bfloat16(v.x), h1 = __float2bfloat16(v.y);
    __nv_bfloat16 h2 = __float2bfloat16(v.z), h3 = __float2bfloat16(v.w);
    uint2 ph;
    ph.x = (unsigned)__bfloat16_as_ushort(h0) | ((unsigned)__bfloat16_as_ushort(h1) << 16);
    ph.y = (unsigned)__bfloat16_as_ushort(h2) | ((unsigned)__bfloat16_as_ushort(h3) << 16);
    return ph;
}

// ---- fp16 row accumulate: acc[0..7] += n * row8 (one uint4 = 8 fp16) ----
__device__ __forceinline__ void acc8(float* acc, uint4 v, float n) {
    float2 f;
    f = __half22float2(*(__half2*)&v.x); acc[0] += n * f.x; acc[1] += n * f.y;
    f = __half22float2(*(__half2*)&v.y); acc[2] += n * f.x; acc[3] += n * f.y;
    f = __half22float2(*(__half2*)&v.z); acc[4] += n * f.x; acc[5] += n * f.y;
    f = __half22float2(*(__half2*)&v.w); acc[6] += n * f.x; acc[7] += n * f.y;
}

// -------- pull-gather on fp16 [x|h] rows (512B/edge) + bf16 conversion + padding --------
// All A writes use st.global.cs (evict-first) so g_xh stays L2-resident.
__global__ __launch_bounds__(256) void gather_k(const float* __restrict__ x,
                                                const float* __restrict__ hprev) {
    int node = blockIdx.x * 8 + (threadIdx.x >> 5);
    int lane = threadIdx.x & 31;
    if (node >= NPAD) return;
    size_t rb = (size_t)node * 128;                       // row base in uint2 units
    uint2* Ah2 = (uint2*)g_Ah;
    uint2* Al2 = (uint2*)g_Al;
    if (node >= NNODES) {                                 // pad rows: zeros
        uint2 z = make_uint2(0u, 0u);
        stcs8(Ah2 + rb + lane, z);        stcs8(Al2 + rb + lane, z);
        stcs8(Ah2 + rb + 32 + lane, z);
        stcs8(Ah2 + rb + 64 + lane, z);   stcs8(Al2 + rb + 64 + lane, z);
        stcs8(Ah2 + rb + 96 + lane, z);
        return;
    }
    int p = csr_off(node);
    int end = (node + 1 < NNODES) ? csr_off(node + 1) : NEDGES;

    const uint4* rows = (const uint4*)g_xh;
    float acc[8];
#pragma unroll
    for (int k = 0; k < 8; k++) acc[k] = 0.f;

    for (; p + 3 < end; p += 4) {
        int2 r0 = g_rec[p],     r1 = g_rec[p + 1];
        int2 r2 = g_rec[p + 2], r3 = g_rec[p + 3];
        uint4 v0 = __ldg(rows + (size_t)r0.x * 32 + lane);
        uint4 v1 = __ldg(rows + (size_t)r1.x * 32 + lane);
        uint4 v2 = __ldg(rows + (size_t)r2.x * 32 + lane);
        uint4 v3 = __ldg(rows + (size_t)r3.x * 32 + lane);
        acc8(acc, v0, __int_as_float(r0.y));
        acc8(acc, v1, __int_as_float(r1.y));
        acc8(acc, v2, __int_as_float(r2.y));
        acc8(acc, v3, __int_as_float(r3.y));
    }
    for (; p < end; p++) {
        int2 r0 = g_rec[p];
        uint4 v0 = __ldg(rows + (size_t)r0.x * 32 + lane);
        acc8(acc, v0, __int_as_float(r0.y));
    }

    // L-block hi-only write: lanes 0..15 -> Lx (col4 32..63), 16..31 -> Lh (96..127)
    {
        int l2 = (lane < 16) ? (32 + 2 * lane) : (96 + 2 * (lane - 16));
        uint2 hi0 = pack_hi_only(make_float4(acc[0], acc[1], acc[2], acc[3]));
        uint2 hi1 = pack_hi_only(make_float4(acc[4], acc[5], acc[6], acc[7]));
        stcs8(Ah2 + rb + l2, hi0);
        stcs8(Ah2 + rb + l2 + 1, hi1);
    }

    // own-row x / h from exact fp32 (col4 0..31 and 64..95) — hi + lo
    {
        float4 vx = ((const float4*)(x + (size_t)node * 128))[lane];
        float4 vh = ((const float4*)(hprev + (size_t)node * 128))[lane];
        uint2 lo, hi;
        hi = pack_hilo(vx, &lo);
        stcs8(Ah2 + rb + lane, hi);       stcs8(Al2 + rb + lane, lo);
        hi = pack_hilo(vh, &lo);
        stcs8(Ah2 + rb + 64 + lane, hi);  stcs8(Al2 + rb + 64 + lane, lo);
    }
}

// ======= cta_group::2 tcgen05 bf16x3 GEMM (pass-interleaved) + LSTM epilogue =======
// al-pass only on K-tiles {0,1,4,5} (x/h columns).
#define STAGE_BYTES 98304
#define SMEM_DATA0  1024
#define SMEM_TOTAL  (SMEM_DATA0 + 2 * STAGE_BYTES)     // 197632
#define NK_TILES    8
#define AL_TILE(t)  (((t) & 2) == 0)                   // t in {0,1,4,5}

__device__ __forceinline__ float sigmoidf_(float v) { return 1.f / (1.f + expf(-v)); }

#if TC_OK
static __device__ __forceinline__ unsigned swz(unsigned off) {
    return off ^ ((off >> 3) & 0x70);
}
static __device__ __forceinline__ void cp16(uint32_t s, const void* g) {
    asm volatile("cp.async.cg.shared.global [%0], [%1], 16;" :: "r"(s), "l"(g));
}
static __device__ __forceinline__ void mbar_wait(uint32_t mbar, uint32_t parity) {
    asm volatile(
        "{\n\t.reg .pred P;\n"
        "W%=:\n\t"
        "mbarrier.try_wait.parity.acquire.cluster.shared::cta.b64 P, [%0], %1, 0x989680;\n\t"
        "@P bra D%=;\n\t"
        "bra W%=;\n"
        "D%=:\n\t}"
        :: "r"(mbar), "r"(parity) : "memory");
}
// idesc cg2 kind::f16: dtype=F32, a/b=BF16, N=256, M=256
#define IDESC_CG2 0x10400490u
#define DESC_BASE ((2ull << 61) | (1ull << 46) | (64ull << 32) | (1ull << 16))
#define MKDESC(a) (DESC_BASE | (((a) >> 4) & 0x3FFF))

static __device__ __forceinline__ void mma_cg2(uint32_t d, uint64_t ad, uint64_t bd, bool en) {
    uint32_t e = en ? 1u : 0u;
    asm volatile(
        "{\n\t.reg .pred p;\n\t"
        "setp.ne.u32 p, %4, 0;\n\t"
        "tcgen05.mma.cta_group::2.kind::f16 [%0], %1, %2, %3, {%5,%5,%5,%5,%5,%5,%5,%5}, p;\n\t}"
        :: "r"(d), "l"(ad), "l"(bd), "r"(IDESC_CG2), "r"(e), "r"(0u) : "memory");
}

static __device__ __forceinline__ void load_tile(uint32_t sbase, int t, int stage,
                                                 int cbase, int rank, int tid) {
    int k0 = t << 6;
    uint32_t sb = sbase + SMEM_DATA0 + stage * STAGE_BYTES;
#pragma unroll
    for (int b = 0; b < 4; b++) {             // B halves: Bh_n0, Bh_n1, Bl_n0, Bl_n1
        const __nv_bfloat16* src = (b < 2) ? g_Wth : g_Wtl;
        int rowbase = ((b & 1) << 8) + rank * 128;
#pragma unroll
        for (int i = 0; i < 4; i++) {
            int q = tid + (i << 8);
            int row = q >> 3, c = q & 7;
            unsigned off = (row << 7) + (c << 4);
            cp16(sb + b * 16384 + swz(off),
                 src + (size_t)(rowbase + row) * 512 + k0 + c * 8);
        }
    }
    {                                         // A-hi: own 128 M-rows
#pragma unroll
        for (int i = 0; i < 4; i++) {
            int q = tid + (i << 8);
            int row = q >> 3, c = q & 7;
            unsigned off = (row << 7) + (c << 4);
            cp16(sb + 65536 + swz(off),
                 g_Ah + (size_t)(cbase + rank * 128 + row) * 512 + k0 + c * 8);
        }
    }
    if (AL_TILE(t)) {                         // A-lo only on x/h tiles
#pragma unroll
        for (int i = 0; i < 4; i++) {
            int q = tid + (i << 8);
            int row = q >> 3, c = q & 7;
            unsigned off = (row << 7) + (c << 4);
            cp16(sb + 81920 + swz(off),
                 g_Al + (size_t)(cbase + rank * 128 + row) * 512 + k0 + c * 8);
        }
    }
    asm volatile("cp.async.commit_group;" ::: "memory");
}
#endif  // TC_OK

__global__ __launch_bounds__(256, 1) __cluster_dims__(2, 1, 1)
void gemm_k(const float* __restrict__ cprev, float* __restrict__ out) {
#if TC_OK
    extern __shared__ __align__(1024) char smem[];
    uint32_t sbase;
    asm("{ .reg .u64 t; cvta.to.shared.u64 t, %1; cvt.u32.u64 %0, t; }"
        : "=r"(sbase) : "l"(smem));
    const int tid = threadIdx.x;
    uint32_t rank;
    asm("mov.u32 %0, %%cluster_ctarank;" : "=r"(rank));
    const int cbase = (blockIdx.x >> 1) << 8;            // cluster row base (256 rows)
    const uint32_t ready = sbase + 8;                    // leader's: count=2
    const uint32_t done  = sbase + 16;                   // per-CTA: count=1 (multicast commit)

    if (tid < 32) {
        asm volatile("tcgen05.alloc.cta_group::2.sync.aligned.shared::cta.b32 [%0], %1;"
                     :: "r"(sbase), "r"(512) : "memory");
        asm volatile("tcgen05.relinquish_alloc_permit.cta_group::2.sync.aligned;");
    }
    if (tid == 0) {
        asm volatile("mbarrier.init.shared.b64 [%0], %1;" :: "r"(ready), "r"(2) : "memory");
        asm volatile("mbarrier.init.shared.b64 [%0], %1;" :: "r"(done), "r"(1) : "memory");
    }
    __syncthreads();
    asm volatile("barrier.cluster.arrive.aligned;" ::: "memory");
    asm volatile("barrier.cluster.wait.aligned;" ::: "memory");

    uint32_t tmem;
    asm("ld.shared.b32 %0, [%1];" : "=r"(tmem) : "r"(sbase));

    load_tile(sbase, 0, 0, cbase, rank, tid);
    for (int t = 0; t < NK_TILES; t++) {
        if (t + 1 < NK_TILES) {
            if (t >= 1) mbar_wait(done, (t - 1) & 1);    // stage (t+1)&1 free
            load_tile(sbase, t + 1, (t + 1) & 1, cbase, rank, tid);
        }
        if (t + 1 < NK_TILES)
            asm volatile("cp.async.wait_group 1;" ::: "memory");
        else
            asm volatile("cp.async.wait_group 0;" ::: "memory");
        asm volatile("fence.proxy.async.shared::cta;" ::: "memory");
        __syncthreads();
        if (tid == 0) {
            asm volatile(
                "{\n\t.reg .b32 r;\n\t"
                "mapa.shared::cluster.u32 r, %0, 0;\n\t"
                "mbarrier.arrive.shared::cluster.b64 _, [r];\n\t}"
                :: "r"(ready) : "memory");
            if (rank == 0) {
                mbar_wait(ready, t & 1);                 // both CTAs' tiles ready
                uint32_t st = sbase + SMEM_DATA0 + (t & 1) * STAGE_BYTES;
                uint64_t bh0 = MKDESC(st);
                uint64_t bh1 = MKDESC(st + 16384);
                uint64_t bl0 = MKDESC(st + 32768);
                uint64_t bl1 = MKDESC(st + 49152);
                uint64_t ah  = MKDESC(st + 65536);
                uint64_t al  = MKDESC(st + 81920);
                const bool do_al = AL_TILE(t);
#pragma unroll
                for (int ks = 0; ks < 4; ks++) {
                    bool acc = !(t == 0 && ks == 0);
                    uint64_t o = ks * 2;
                    mma_cg2(tmem,       ah + o, bh0 + o, acc);
                    mma_cg2(tmem + 256, ah + o, bh1 + o, acc);
                    mma_cg2(tmem,       ah + o, bl0 + o, true);
                    mma_cg2(tmem + 256, ah + o, bl1 + o, true);
                    if (do_al) {
                        mma_cg2(tmem,       al + o, bh0 + o, true);
                        mma_cg2(tmem + 256, al + o, bh1 + o, true);
                    }
                }
                asm volatile(
                    "tcgen05.commit.cta_group::2.mbarrier::arrive::one.shared::cluster.multicast::cluster.b64 [%0], %1;"
                    :: "r"(done), "h"((uint16_t)0x3) : "memory");
            }
        }
    }
    mbar_wait(done, 0);                                  // tile 6
    mbar_wait(done, 1);                                  // tile 7
    asm volatile("tcgen05.fence::after_thread_sync;" ::: "memory");
    __syncthreads();

    // ---- fused LSTM epilogue: 8 warps, direct streaming float4 stores ----
    {
        const int row = tid & 127;
        const int colbase = (tid >> 7) << 6;             // 0 or 64
        const int grow = cbase + (int)rank * 128 + row;
        const bool ok = grow < NNODES;
        float* oh = out + (size_t)grow * 128;
        float* oc = oh + (size_t)NNODES * 128;
        const float4* cp4base = (const float4*)(cprev + (size_t)grow * 128);

#pragma unroll 1
        for (int ch = 0; ch < 4; ch++) {
            const int c0 = colbase + ch * 16;
            uint32_t ri[16], rf[16], rg[16], ro[16];
            #define LD16(arr, addr) \
                asm volatile("tcgen05.ld.sync.aligned.32x32b.x16.b32 " \
                    "{%0,%1,%2,%3,%4,%5,%6,%7,%8,%9,%10,%11,%12,%13,%14,%15}, [%16];" \
                    : "=r"(arr[0]),"=r"(arr[1]),"=r"(arr[2]),"=r"(arr[3]), \
                      "=r"(arr[4]),"=r"(arr[5]),"=r"(arr[6]),"=r"(arr[7]), \
                      "=r"(arr[8]),"=r"(arr[9]),"=r"(arr[10]),"=r"(arr[11]), \
                      "=r"(arr[12]),"=r"(arr[13]),"=r"(arr[14]),"=r"(arr[15]) \
                    : "r"(addr))
            LD16(ri, tmem +   0 + c0);
            LD16(rf, tmem + 128 + c0);
            LD16(rg, tmem + 256 + c0);
            LD16(ro, tmem + 384 + c0);
            #undef LD16
            asm volatile("tcgen05.wait::ld.sync.aligned;" ::: "memory");

            float cpv[16];
            if (ok) {
#pragma unroll
                for (int q = 0; q < 4; q++)
                    *(float4*)&cpv[q * 4] = cp4base[(c0 >> 2) + q];
            } else {
#pragma unroll
                for (int q = 0; q < 16; q++) cpv[q] = 0.f;
            }

            float hv[16], cv[16];
#pragma unroll
            for (int j = 0; j < 16; j++) {
                int col = c0 + j;
                float gi = __uint_as_float(ri[j]) + g_bias[col];
                float gf = __uint_as_float(rf[j]) + g_bias[128 + col];
                float gg = __uint_as_float(rg[j]) + g_bias[256 + col];
                float go = __uint_as_float(ro[j]) + g_bias[384 + col];
                float c = sigmoidf_(gf) * cpv[j] + sigmoidf_(gi) * tanhf(gg);
                cv[j] = c;
                hv[j] = sigmoidf_(go) * tanhf(c);
            }
            if (ok) {
#pragma unroll
                for (int j = 0; j < 16; j += 4) {
                    stcs16(oh + c0 + j, make_float4(hv[j], hv[j+1], hv[j+2], hv[j+3]));
                    stcs16(oc + c0 + j, make_float4(cv[j], cv[j+1], cv[j+2], cv[j+3]));
                }
            }
        }
        asm volatile("tcgen05.fence::before_thread_sync;" ::: "memory");
    }
    __syncthreads();
    if (tid < 32) {
        asm volatile("tcgen05.dealloc.cta_group::2.sync.aligned.b32 %0, %1;"
                     :: "r"(tmem), "r"(512));
    }
    asm volatile("barrier.cluster.arrive.aligned;" ::: "memory");
    asm volatile("barrier.cluster.wait.aligned;" ::: "memory");

#else  // !TC_OK — correct scalar fallback for the non-sm_103a pass (never run).
    const int tid = threadIdx.x;
    const int bm = blockIdx.x * 128;
    for (int idx = tid; idx < 128 * 128; idx += 256) {
        int row = idx >> 7, col = idx & 127;
        int grow = bm + row;
        if (grow >= NNODES) continue;
        float acc0 = g_bias[col], acc1 = g_bias[128 + col];
        float acc2 = g_bias[256 + col], acc3 = g_bias[384 + col];
        for (int k = 0; k < 512; k++) {
            int part = k >> 7;
            float al = (part == 0 || part == 2)
                       ? __bfloat162float(g_Al[(size_t)grow * 512 + k]) : 0.f;
            float a = __bfloat162float(g_Ah[(size_t)grow * 512 + k]) + al;
            acc0 += a * (__bfloat162float(g_Wth[(size_t)(0 * 128 + col) * 512 + k]) +
                         __bfloat162float(g_Wtl[(size_t)(0 * 128 + col) * 512 + k]));
            acc1 += a * (__bfloat162float(g_Wth[(size_t)(1 * 128 + col) * 512 + k]) +
                         __bfloat162float(g_Wtl[(size_t)(1 * 128 + col) * 512 + k]));
            acc2 += a * (__bfloat162float(g_Wth[(size_t)(2 * 128 + col) * 512 + k]) +
                         __bfloat162float(g_Wtl[(size_t)(2 * 128 + col) * 512 + k]));
            acc3 += a * (__bfloat162float(g_Wth[(size_t)(3 * 128 + col) * 512 + k]) +
                         __bfloat162float(g_Wtl[(size_t)(3 * 128 + col) * 512 + k]));
        }
        float c = sigmoidf_(acc1) * cprev[(size_t)grow * 128 + col] +
                  sigmoidf_(acc0) * tanhf(acc2);
        out[(size_t)grow * 128 + col] = sigmoidf_(acc3) * tanhf(c);
        out[(size_t)NNODES * 128 + (size_t)grow * 128 + col] = c;
    }
#endif  // TC_OK
}

// ---------------- launch ----------------
extern "C" void kernel_launch(void* const* d_in, const int* in_sizes, int n_in,
                              void* d_out, int out_size) {
    const float* x     = (const float*)d_in[0];
    const void*  ei    = d_in[1];
    const float* ew    = (const float*)d_in[2];
    const float* hprev = (const float*)d_in[3];
    const float* cprev = (const float*)d_in[4];
    const float* Wx0   = (const float*)d_in[5];
    const float* Wx1   = (const float*)d_in[6];
    const float* Wh0   = (const float*)d_in[7];
    const float* Wh1   = (const float*)d_in[8];
    const float* bx    = (const float*)d_in[9];
    const float* bh    = (const float*)d_in[10];

    cudaFuncSetAttribute(gemm_k, cudaFuncAttributeMaxDynamicSharedMemorySize, SMEM_TOTAL);

    prep_k<<<(NNODES + 7) / 8, 256>>>(ei, x, hprev);
    buildw_k<<<(512 * 512 + 255) / 256, 256>>>(Wx0, Wx1, Wh0, Wh1, bx, bh);
    deg_k<<<(NEDGES / 4 + 255) / 256, 256>>>(ei, ew);
    scan1_k<<<SCAN_BLOCKS, 256>>>();
    scan2_k<<<1, 512>>>();
    fill_k<<<(NEDGES / 4 + 255) / 256, 256>>>(ei, ew);
    gather_k<<<(NPAD + 7) / 8, 256>>>(x, hprev);
    gemm_k<<<NCTAS, 256, SMEM_TOTAL>>>(cprev, (float*)d_out);
}

// round 14
// speedup vs baseline: 1.0001x; 1.0001x over previous
#include <cuda_runtime.h>
#include <cuda_bf16.h>
#include <cuda_fp16.h>
#include <math.h>
#include <stdint.h>

#define NNODES 100000
#define NEDGES 1600000
#define NPAD   100096          // 391 clusters * 256 rows
#define SCAN_BLOCKS 391        // ceil(NNODES/256)
#define CL_SPLIT 196           // clusters in part A
#define NODE_SPLIT (CL_SPLIT * 256)   // 50176

// Arch-specific guard: tcgen05 only exists in the sm_103a / family-specific pass.
#ifndef __CUDA_ARCH_FAMILY_SPECIFIC__
#define __CUDA_ARCH_FAMILY_SPECIFIC__ 0
#endif
#ifndef __CUDA_ARCH_SPECIFIC__
#define __CUDA_ARCH_SPECIFIC__ 0
#endif
#if defined(__CUDA_ARCH__) && (defined(__CUDA_ARCH_FEAT_SM103_ALL) || \
    (__CUDA_ARCH_FAMILY_SPECIFIC__ == 1030) || (__CUDA_ARCH_SPECIFIC__ == 1030))
#define TC_OK 1
#else
#define TC_OK 0
#endif

// ---------------- device scratch (static, no allocation) ----------------
__device__ float g_dis[NNODES];
__device__ int   g_cnt[NNODES];
__device__ int   g_loc[NNODES];
__device__ int   g_bsum[512];
__device__ int   g_cur[NNODES];
__device__ int2  g_rec[NEDGES];                      // packed {src, norm-as-int}
__device__ __half g_xh[(size_t)NNODES * 256];        // fp16 [x row | h row], 512B/node
__device__ __nv_bfloat16 g_Ah[(size_t)NPAD * 512];   // [x|Lx|h|Lh] hi
__device__ __nv_bfloat16 g_Al[(size_t)NPAD * 512];   // lo residual (x/h cols only)
__device__ __nv_bfloat16 g_Wth[512 * 512];           // W^T hi  [outcol][k]
__device__ __nv_bfloat16 g_Wtl[512 * 512];           // W^T lo
__device__ float g_bias[512];
__device__ int   g_idx64;

__device__ __forceinline__ int get_idx(const void* ei, long long pos) {
    if (g_idx64) return (int)((const long long*)ei)[pos];
    return ((const int*)ei)[pos];
}

// streaming (evict-first) 8B / 16B stores
__device__ __forceinline__ void stcs8(void* p, uint2 v) {
    unsigned long long u = (unsigned long long)v.x | ((unsigned long long)v.y << 32);
    asm volatile("st.global.cs.b64 [%0], %1;" :: "l"(p), "l"(u) : "memory");
}
__device__ __forceinline__ void stcs16(void* p, float4 v) {
    asm volatile("st.global.cs.v4.f32 [%0], {%1,%2,%3,%4};"
                 :: "l"(p), "f"(v.x), "f"(v.y), "f"(v.z), "f"(v.w) : "memory");
}

// ------- zero accumulators + edge dtype detection + fp16 [x|h] row packing -------
__global__ void prep_k(const void* ei, const float* __restrict__ x,
                       const float* __restrict__ hprev) {
    int tid = threadIdx.x;
    int i = blockIdx.x * 256 + tid;
    if (i < NNODES) { g_dis[i] = 0.f; g_cnt[i] = 0; g_cur[i] = 0; }
    if (blockIdx.x == 0 && tid == 0) {
        const unsigned long long* p = (const unsigned long long*)ei;
        int ok64 = 1;
        for (int k = 0; k < 256; k++)
            if (p[k] >= (unsigned long long)NNODES) { ok64 = 0; break; }
        g_idx64 = ok64;
    }
    int node = blockIdx.x * 8 + (tid >> 5);
    int lane = tid & 31;
    if (node < NNODES) {
        float4 vx = ((const float4*)(x + (size_t)node * 128))[lane];
        float4 vh = ((const float4*)(hprev + (size_t)node * 128))[lane];
        __half2 x01 = __floats2half2_rn(vx.x, vx.y);
        __half2 x23 = __floats2half2_rn(vx.z, vx.w);
        __half2 h01 = __floats2half2_rn(vh.x, vh.y);
        __half2 h23 = __floats2half2_rn(vh.z, vh.w);
        uint2 px, ph;
        px.x = *(unsigned*)&x01; px.y = *(unsigned*)&x23;
        ph.x = *(unsigned*)&h01; ph.y = *(unsigned*)&h23;
        ((uint2*)g_xh)[(size_t)node * 64 + lane] = px;        // x: bytes 0..255
        ((uint2*)g_xh)[(size_t)node * 64 + 32 + lane] = ph;   // h: bytes 256..511
    }
}

// ---------------- pack W^T in bf16 hi/lo + bias ----------------
__global__ void buildw_k(const float* __restrict__ Wx0, const float* __restrict__ Wx1,
                         const float* __restrict__ Wh0, const float* __restrict__ Wh1,
                         const float* __restrict__ bx,  const float* __restrict__ bh) {
    int idx = blockIdx.x * blockDim.x + threadIdx.x;
    if (idx >= 512 * 512) return;
    int c = idx >> 9;        // k index
    int j = idx & 511;       // output col
    int g = j >> 7;
    int h = j & 127;
    int part = c >> 7;
    int cc = c & 127;
    const float* W = (part == 0) ? Wx0 : (part == 1) ? Wx1 : (part == 2) ? Wh0 : Wh1;
    float wv = W[((size_t)g * 128 + cc) * 128 + h];
    __nv_bfloat16 hi = __float2bfloat16(wv);
    float lo = wv - __bfloat162float(hi);
    g_Wth[(size_t)j * 512 + c] = hi;
    g_Wtl[(size_t)j * 512 + c] = __float2bfloat16(lo);
    if (c == 0) g_bias[j] = bx[g * 128 + h] + bh[g * 128 + h];
}

// ------- degree (sum w over src) + in-degree count (dst), 4 edges/thread -------
__global__ void deg_k(const void* __restrict__ ei, const float* __restrict__ w) {
    int e0 = (blockIdx.x * blockDim.x + threadIdx.x) * 4;
    if (e0 >= NEDGES) return;                 // NEDGES % 4 == 0
    int s[4], d[4];
    float ww[4];
#pragma unroll
    for (int i = 0; i < 4; i++) {
        s[i] = get_idx(ei, e0 + i);
        d[i] = get_idx(ei, (long long)NEDGES + e0 + i);
        ww[i] = w[e0 + i];
    }
#pragma unroll
    for (int i = 0; i < 4; i++) {
        atomicAdd(&g_dis[s[i]], ww[i]);
        atomicAdd(&g_cnt[d[i]], 1);
    }
}

// -------- scan pass 1 (per-block exclusive scan of g_cnt) + fused deg^{-1/2} --------
__global__ void scan1_k() {
    __shared__ int s[256];
    int tid = threadIdx.x;
    int i = blockIdx.x * 256 + tid;
    if (i < NNODES) {
        float d = g_dis[i];
        g_dis[i] = (d > 0.f) ? rsqrtf(d) : 0.f;
    }
    int v = (i < NNODES) ? g_cnt[i] : 0;
    s[tid] = v;
    __syncthreads();
#pragma unroll
    for (int o = 1; o < 256; o <<= 1) {
        int t = (tid >= o) ? s[tid - o] : 0;
        __syncthreads();
        s[tid] += t;
        __syncthreads();
    }
    if (i < NNODES) g_loc[i] = s[tid] - v;
    if (tid == 255) g_bsum[blockIdx.x] = s[255];
}
__global__ void scan2_k() {
    __shared__ int s[512];
    int tid = threadIdx.x;
    int v = (tid < SCAN_BLOCKS) ? g_bsum[tid] : 0;
    s[tid] = v;
    __syncthreads();
#pragma unroll
    for (int o = 1; o < 512; o <<= 1) {
        int t = (tid >= o) ? s[tid - o] : 0;
        __syncthreads();
        s[tid] += t;
        __syncthreads();
    }
    if (tid < SCAN_BLOCKS) g_bsum[tid] = s[tid] - v;
}
__device__ __forceinline__ int csr_off(int node) {
    return g_bsum[node >> 8] + g_loc[node];
}

// ------- fill packed CSR records {src, norm} grouped by dst, 4 edges/thread -------
__global__ void fill_k(const void* __restrict__ ei, const float* __restrict__ w) {
    int e0 = (blockIdx.x * blockDim.x + threadIdx.x) * 4;
    if (e0 >= NEDGES) return;
    int s[4], d[4];
    float ww[4];
#pragma unroll
    for (int i = 0; i < 4; i++) {
        s[i] = get_idx(ei, e0 + i);
        d[i] = get_idx(ei, (long long)NEDGES + e0 + i);
        ww[i] = w[e0 + i];
    }
    float dis_s[4], dis_d[4];
#pragma unroll
    for (int i = 0; i < 4; i++) { dis_s[i] = g_dis[s[i]]; dis_d[i] = g_dis[d[i]]; }
#pragma unroll
    for (int i = 0; i < 4; i++) {
        float nm = -(dis_s[i] * ww[i] * dis_d[i]);
        int pos = csr_off(d[i]) + atomicAdd(&g_cur[d[i]], 1);
        g_rec[pos] = make_int2(s[i], __float_as_int(nm));
    }
}

// ---------------- bf16 hi/lo pack helpers ----------------
__device__ __forceinline__ uint2 pack_hilo(float4 v, uint2* lo) {
    __nv_bfloat16 h0 = __float2bfloat16(v.x), h1 = __float2bfloat16(v.y);
    __nv_bfloat16 h2 = __float2bfloat16(v.z), h3 = __float2bfloat16(v.w);
    __nv_bfloat16 l0 = __float2bfloat16(v.x - __bfloat162float(h0));
    __nv_bfloat16 l1 = __float2bfloat16(v.y - __bfloat162float(h1));
    __nv_bfloat16 l2 = __float2bfloat16(v.z - __bfloat162float(h2));
    __nv_bfloat16 l3 = __float2bfloat16(v.w - __bfloat162float(h3));
    uint2 ph;
    ph.x = (unsigned)__bfloat16_as_ushort(h0) | ((unsigned)__bfloat16_as_ushort(h1) << 16);
    ph.y = (unsigned)__bfloat16_as_ushort(h2) | ((unsigned)__bfloat16_as_ushort(h3) << 16);
    lo->x = (unsigned)__bfloat16_as_ushort(l0) | ((unsigned)__bfloat16_as_ushort(l1) << 16);
    lo->y = (unsigned)__bfloat16_as_ushort(l2) | ((unsigned)__bfloat16_as_ushort(l3) << 16);
    return ph;
}
__device__ __forceinline__ uint2 pack_hi_only(float4 v) {
    __nv_bfloat16 h0 = __float2bfloat16(v.x), h1 = __float2bfloat16(v.y);
    __nv_bfloat16 h2 = __float2bfloat16(v.z), h3 = __float2bfloat16(v.w);
    uint2 ph;
    ph.x = (unsigned)__bfloat16_as_ushort(h0) | ((unsigned)__bfloat16_as_ushort(h1) << 16);
    ph.y = (unsigned)__bfloat16_as_ushort(h2) | ((unsigned)__bfloat16_as_ushort(h3) << 16);
    return ph;
}

// ---- fp16 row accumulate: acc[0..7] += n * row8 (one uint4 = 8 fp16) ----
__device__ __forceinline__ void acc8(float* acc, uint4 v, float n) {
    float2 f;
    f = __half22float2(*(__half2*)&v.x); acc[0] += n * f.x; acc[1] += n * f.y;
    f = __half22float2(*(__half2*)&v.y); acc[2] += n * f.x; acc[3] += n * f.y;
    f = __half22float2(*(__half2*)&v.z); acc[4] += n * f.x; acc[5] += n * f.y;
    f = __half22float2(*(__half2*)&v.w); acc[6] += n * f.x; acc[7] += n * f.y;
}

// -------- pull-gather on fp16 [x|h] rows (512B/edge) + bf16 conversion + padding --------
__global__ __launch_bounds__(256) void gather_k(int node_base,
                                                const float* __restrict__ x,
                                                const float* __restrict__ hprev) {
    int node = node_base + blockIdx.x * 8 + (threadIdx.x >> 5);
    int lane = threadIdx.x & 31;
    if (node >= NPAD) return;
    size_t rb = (size_t)node * 128;                       // row base in uint2 units
    uint2* Ah2 = (uint2*)g_Ah;
    uint2* Al2 = (uint2*)g_Al;
    if (node >= NNODES) {                                 // pad rows: zeros
        uint2 z = make_uint2(0u, 0u);
        stcs8(Ah2 + rb + lane, z);        stcs8(Al2 + rb + lane, z);
        stcs8(Ah2 + rb + 32 + lane, z);
        stcs8(Ah2 + rb + 64 + lane, z);   stcs8(Al2 + rb + 64 + lane, z);
        stcs8(Ah2 + rb + 96 + lane, z);
        return;
    }
    int p = csr_off(node);
    int end = (node + 1 < NNODES) ? csr_off(node + 1) : NEDGES;

    const uint4* rows = (const uint4*)g_xh;
    float acc[8];
#pragma unroll
    for (int k = 0; k < 8; k++) acc[k] = 0.f;

    for (; p + 3 < end; p += 4) {
        int2 r0 = g_rec[p],     r1 = g_rec[p + 1];
        int2 r2 = g_rec[p + 2], r3 = g_rec[p + 3];
        uint4 v0 = __ldg(rows + (size_t)r0.x * 32 + lane);
        uint4 v1 = __ldg(rows + (size_t)r1.x * 32 + lane);
        uint4 v2 = __ldg(rows + (size_t)r2.x * 32 + lane);
        uint4 v3 = __ldg(rows + (size_t)r3.x * 32 + lane);
        acc8(acc, v0, __int_as_float(r0.y));
        acc8(acc, v1, __int_as_float(r1.y));
        acc8(acc, v2, __int_as_float(r2.y));
        acc8(acc, v3, __int_as_float(r3.y));
    }
    for (; p < end; p++) {
        int2 r0 = g_rec[p];
        uint4 v0 = __ldg(rows + (size_t)r0.x * 32 + lane);
        acc8(acc, v0, __int_as_float(r0.y));
    }

    // L-block hi-only write: lanes 0..15 -> Lx (col4 32..63), 16..31 -> Lh (96..127)
    {
        int l2 = (lane < 16) ? (32 + 2 * lane) : (96 + 2 * (lane - 16));
        uint2 hi0 = pack_hi_only(make_float4(acc[0], acc[1], acc[2], acc[3]));
        uint2 hi1 = pack_hi_only(make_float4(acc[4], acc[5], acc[6], acc[7]));
        stcs8(Ah2 + rb + l2, hi0);
        stcs8(Ah2 + rb + l2 + 1, hi1);
    }

    // own-row x / h from exact fp32 (col4 0..31 and 64..95) — hi + lo
    {
        float4 vx = ((const float4*)(x + (size_t)node * 128))[lane];
        float4 vh = ((const float4*)(hprev + (size_t)node * 128))[lane];
        uint2 lo, hi;
        hi = pack_hilo(vx, &lo);
        stcs8(Ah2 + rb + lane, hi);       stcs8(Al2 + rb + lane, lo);
        hi = pack_hilo(vh, &lo);
        stcs8(Ah2 + rb + 64 + lane, hi);  stcs8(Al2 + rb + 64 + lane, lo);
    }
}

// ======= cta_group::2 tcgen05 bf16x3 GEMM (pass-interleaved) + LSTM epilogue =======
#define STAGE_BYTES 98304
#define SMEM_DATA0  1024
#define SMEM_TOTAL  (SMEM_DATA0 + 2 * STAGE_BYTES)     // 197632
#define NK_TILES    8
#define AL_TILE(t)  (((t) & 2) == 0)                   // t in {0,1,4,5}

__device__ __forceinline__ float sigmoidf_(float v) { return 1.f / (1.f + expf(-v)); }

#if TC_OK
static __device__ __forceinline__ unsigned swz(unsigned off) {
    return off ^ ((off >> 3) & 0x70);
}
static __device__ __forceinline__ void cp16(uint32_t s, const void* g) {
    asm volatile("cp.async.cg.shared.global [%0], [%1], 16;" :: "r"(s), "l"(g));
}
static __device__ __forceinline__ void mbar_wait(uint32_t mbar, uint32_t parity) {
    asm volatile(
        "{\n\t.reg .pred P;\n"
        "W%=:\n\t"
        "mbarrier.try_wait.parity.acquire.cluster.shared::cta.b64 P, [%0], %1, 0x989680;\n\t"
        "@P bra D%=;\n\t"
        "bra W%=;\n"
        "D%=:\n\t}"
        :: "r"(mbar), "r"(parity) : "memory");
}
// idesc cg2 kind::f16: dtype=F32, a/b=BF16, N=256, M=256
#define IDESC_CG2 0x10400490u
#define DESC_BASE ((2ull << 61) | (1ull << 46) | (64ull << 32) | (1ull << 16))
#define MKDESC(a) (DESC_BASE | (((a) >> 4) & 0x3FFF))

static __device__ __forceinline__ void mma_cg2(uint32_t d, uint64_t ad, uint64_t bd, bool en) {
    uint32_t e = en ? 1u : 0u;
    asm volatile(
        "{\n\t.reg .pred p;\n\t"
        "setp.ne.u32 p, %4, 0;\n\t"
        "tcgen05.mma.cta_group::2.kind::f16 [%0], %1, %2, %3, {%5,%5,%5,%5,%5,%5,%5,%5}, p;\n\t}"
        :: "r"(d), "l"(ad), "l"(bd), "r"(IDESC_CG2), "r"(e), "r"(0u) : "memory");
}

static __device__ __forceinline__ void load_tile(uint32_t sbase, int t, int stage,
                                                 int cbase, int rank, int tid) {
    int k0 = t << 6;
    uint32_t sb = sbase + SMEM_DATA0 + stage * STAGE_BYTES;
#pragma unroll
    for (int b = 0; b < 4; b++) {             // B halves: Bh_n0, Bh_n1, Bl_n0, Bl_n1
        const __nv_bfloat16* src = (b < 2) ? g_Wth : g_Wtl;
        int rowbase = ((b & 1) << 8) + rank * 128;
#pragma unroll
        for (int i = 0; i < 4; i++) {
            int q = tid + (i << 8);
            int row = q >> 3, c = q & 7;
            unsigned off = (row << 7) + (c << 4);
            cp16(sb + b * 16384 + swz(off),
                 src + (size_t)(rowbase + row) * 512 + k0 + c * 8);
        }
    }
    {                                         // A-hi: own 128 M-rows
#pragma unroll
        for (int i = 0; i < 4; i++) {
            int q = tid + (i << 8);
            int row = q >> 3, c = q & 7;
            unsigned off = (row << 7) + (c << 4);
            cp16(sb + 65536 + swz(off),
                 g_Ah + (size_t)(cbase + rank * 128 + row) * 512 + k0 + c * 8);
        }
    }
    if (AL_TILE(t)) {                         // A-lo only on x/h tiles
#pragma unroll
        for (int i = 0; i < 4; i++) {
            int q = tid + (i << 8);
            int row = q >> 3, c = q & 7;
            unsigned off = (row << 7) + (c << 4);
            cp16(sb + 81920 + swz(off),
                 g_Al + (size_t)(cbase + rank * 128 + row) * 512 + k0 + c * 8);
        }
    }
    asm volatile("cp.async.commit_group;" ::: "memory");
}
#endif  // TC_OK

__global__ __launch_bounds__(256, 1) __cluster_dims__(2, 1, 1)
void gemm_k(int cluster_base, const float* __restrict__ cprev, float* __restrict__ out) {
#if TC_OK
    extern __shared__ __align__(1024) char smem[];
    uint32_t sbase;
    asm("{ .reg .u64 t; cvta.to.shared.u64 t, %1; cvt.u32.u64 %0, t; }"
        : "=r"(sbase) : "l"(smem));
    const int tid = threadIdx.x;
    uint32_t rank;
    asm("mov.u32 %0, %%cluster_ctarank;" : "=r"(rank));
    const int cbase = ((blockIdx.x >> 1) + cluster_base) << 8;   // cluster row base
    const uint32_t ready = sbase + 8;                    // leader's: count=2
    const uint32_t done  = sbase + 16;                   // per-CTA: count=1 (multicast commit)

    if (tid < 32) {
        asm volatile("tcgen05.alloc.cta_group::2.sync.aligned.shared::cta.b32 [%0], %1;"
                     :: "r"(sbase), "r"(512) : "memory");
        asm volatile("tcgen05.relinquish_alloc_permit.cta_group::2.sync.aligned;");
    }
    if (tid == 0) {
        asm volatile("mbarrier.init.shared.b64 [%0], %1;" :: "r"(ready), "r"(2) : "memory");
        asm volatile("mbarrier.init.shared.b64 [%0], %1;" :: "r"(done), "r"(1) : "memory");
    }
    __syncthreads();
    asm volatile("barrier.cluster.arrive.aligned;" ::: "memory");
    asm volatile("barrier.cluster.wait.aligned;" ::: "memory");

    uint32_t tmem;
    asm("ld.shared.b32 %0, [%1];" : "=r"(tmem) : "r"(sbase));

    load_tile(sbase, 0, 0, cbase, rank, tid);
    for (int t = 0; t < NK_TILES; t++) {
        if (t + 1 < NK_TILES) {
            if (t >= 1) mbar_wait(done, (t - 1) & 1);    // stage (t+1)&1 free
            load_tile(sbase, t + 1, (t + 1) & 1, cbase, rank, tid);
        }
        if (t + 1 < NK_TILES)
            asm volatile("cp.async.wait_group 1;" ::: "memory");
        else
            asm volatile("cp.async.wait_group 0;" ::: "memory");
        asm volatile("fence.proxy.async.shared::cta;" ::: "memory");
        __syncthreads();
        if (tid == 0) {
            asm volatile(
                "{\n\t.reg .b32 r;\n\t"
                "mapa.shared::cluster.u32 r, %0, 0;\n\t"
                "mbarrier.arrive.shared::cluster.b64 _, [r];\n\t}"
                :: "r"(ready) : "memory");
            if (rank == 0) {
                mbar_wait(ready, t & 1);                 // both CTAs' tiles ready
                uint32_t st = sbase + SMEM_DATA0 + (t & 1) * STAGE_BYTES;
                uint64_t bh0 = MKDESC(st);
                uint64_t bh1 = MKDESC(st + 16384);
                uint64_t bl0 = MKDESC(st + 32768);
                uint64_t bl1 = MKDESC(st + 49152);
                uint64_t ah  = MKDESC(st + 65536);
                uint64_t al  = MKDESC(st + 81920);
                const bool do_al = AL_TILE(t);
#pragma unroll
                for (int ks = 0; ks < 4; ks++) {
                    bool acc = !(t == 0 && ks == 0);
                    uint64_t o = ks * 2;
                    mma_cg2(tmem,       ah + o, bh0 + o, acc);
                    mma_cg2(tmem + 256, ah + o, bh1 + o, acc);
                    mma_cg2(tmem,       ah + o, bl0 + o, true);
                    mma_cg2(tmem + 256, ah + o, bl1 + o, true);
                    if (do_al) {
                        mma_cg2(tmem,       al + o, bh0 + o, true);
                        mma_cg2(tmem + 256, al + o, bh1 + o, true);
                    }
                }
                asm volatile(
                    "tcgen05.commit.cta_group::2.mbarrier::arrive::one.shared::cluster.multicast::cluster.b64 [%0], %1;"
                    :: "r"(done), "h"((uint16_t)0x3) : "memory");
            }
        }
    }
    mbar_wait(done, 0);                                  // tile 6
    mbar_wait(done, 1);                                  // tile 7
    asm volatile("tcgen05.fence::after_thread_sync;" ::: "memory");
    __syncthreads();

    // ---- fused LSTM epilogue: 8 warps, direct streaming float4 stores ----
    {
        const int row = tid & 127;
        const int colbase = (tid >> 7) << 6;             // 0 or 64
        const int grow = cbase + (int)rank * 128 + row;
        const bool ok = grow < NNODES;
        float* oh = out + (size_t)grow * 128;
        float* oc = oh + (size_t)NNODES * 128;
        const float4* cp4base = (const float4*)(cprev + (size_t)grow * 128);

#pragma unroll 1
        for (int ch = 0; ch < 4; ch++) {
            const int c0 = colbase + ch * 16;
            uint32_t ri[16], rf[16], rg[16], ro[16];
            #define LD16(arr, addr) \
                asm volatile("tcgen05.ld.sync.aligned.32x32b.x16.b32 " \
                    "{%0,%1,%2,%3,%4,%5,%6,%7,%8,%9,%10,%11,%12,%13,%14,%15}, [%16];" \
                    : "=r"(arr[0]),"=r"(arr[1]),"=r"(arr[2]),"=r"(arr[3]), \
                      "=r"(arr[4]),"=r"(arr[5]),"=r"(arr[6]),"=r"(arr[7]), \
                      "=r"(arr[8]),"=r"(arr[9]),"=r"(arr[10]),"=r"(arr[11]), \
                      "=r"(arr[12]),"=r"(arr[13]),"=r"(arr[14]),"=r"(arr[15]) \
                    : "r"(addr))
            LD16(ri, tmem +   0 + c0);
            LD16(rf, tmem + 128 + c0);
            LD16(rg, tmem + 256 + c0);
            LD16(ro, tmem + 384 + c0);
            #undef LD16
            asm volatile("tcgen05.wait::ld.sync.aligned;" ::: "memory");

            float cpv[16];
            if (ok) {
#pragma unroll
                for (int q = 0; q < 4; q++)
                    *(float4*)&cpv[q * 4] = cp4base[(c0 >> 2) + q];
            } else {
#pragma unroll
                for (int q = 0; q < 16; q++) cpv[q] = 0.f;
            }

            float hv[16], cv[16];
#pragma unroll
            for (int j = 0; j < 16; j++) {
                int col = c0 + j;
                float gi = __uint_as_float(ri[j]) + g_bias[col];
                float gf = __uint_as_float(rf[j]) + g_bias[128 + col];
                float gg = __uint_as_float(rg[j]) + g_bias[256 + col];
                float go = __uint_as_float(ro[j]) + g_bias[384 + col];
                float c = sigmoidf_(gf) * cpv[j] + sigmoidf_(gi) * tanhf(gg);
                cv[j] = c;
                hv[j] = sigmoidf_(go) * tanhf(c);
            }
            if (ok) {
#pragma unroll
                for (int j = 0; j < 16; j += 4) {
                    stcs16(oh + c0 + j, make_float4(hv[j], hv[j+1], hv[j+2], hv[j+3]));
                    stcs16(oc + c0 + j, make_float4(cv[j], cv[j+1], cv[j+2], cv[j+3]));
                }
            }
        }
        asm volatile("tcgen05.fence::before_thread_sync;" ::: "memory");
    }
    __syncthreads();
    if (tid < 32) {
        asm volatile("tcgen05.dealloc.cta_group::2.sync.aligned.b32 %0, %1;"
                     :: "r"(tmem), "r"(512));
    }
    asm volatile("barrier.cluster.arrive.aligned;" ::: "memory");
    asm volatile("barrier.cluster.wait.aligned;" ::: "memory");

#else  // !TC_OK — correct scalar fallback for the non-sm_103a pass (never run).
    const int tid = threadIdx.x;
    const int bm = (blockIdx.x + cluster_base * 2) * 128;
    for (int idx = tid; idx < 128 * 128; idx += 256) {
        int row = idx >> 7, col = idx & 127;
        int grow = bm + row;
        if (grow >= NNODES) continue;
        float acc0 = g_bias[col], acc1 = g_bias[128 + col];
        float acc2 = g_bias[256 + col], acc3 = g_bias[384 + col];
        for (int k = 0; k < 512; k++) {
            int part = k >> 7;
            float al = (part == 0 || part == 2)
                       ? __bfloat162float(g_Al[(size_t)grow * 512 + k]) : 0.f;
            float a = __bfloat162float(g_Ah[(size_t)grow * 512 + k]) + al;
            acc0 += a * (__bfloat162float(g_Wth[(size_t)(0 * 128 + col) * 512 + k]) +
                         __bfloat162float(g_Wtl[(size_t)(0 * 128 + col) * 512 + k]));
            acc1 += a * (__bfloat162float(g_Wth[(size_t)(1 * 128 + col) * 512 + k]) +
                         __bfloat162float(g_Wtl[(size_t)(1 * 128 + col) * 512 + k]));
            acc2 += a * (__bfloat162float(g_Wth[(size_t)(2 * 128 + col) * 512 + k]) +
                         __bfloat162float(g_Wtl[(size_t)(2 * 128 + col) * 512 + k]));
            acc3 += a * (__bfloat162float(g_Wth[(size_t)(3 * 128 + col) * 512 + k]) +
                         __bfloat162float(g_Wtl[(size_t)(3 * 128 + col) * 512 + k]));
        }
        float c = sigmoidf_(acc1) * cprev[(size_t)grow * 128 + col] +
                  sigmoidf_(acc0) * tanhf(acc2);
        out[(size_t)grow * 128 + col] = sigmoidf_(acc3) * tanhf(c);
        out[(size_t)NNODES * 128 + (size_t)grow * 128 + col] = c;
    }
#endif  // TC_OK
}

// ---------------- launch: stream-forked DAG (graph-capture safe) ----------------
extern "C" void kernel_launch(void* const* d_in, const int* in_sizes, int n_in,
                              void* d_out, int out_size) {
    const float* x     = (const float*)d_in[0];
    const void*  ei    = d_in[1];
    const float* ew    = (const float*)d_in[2];
    const float* hprev = (const float*)d_in[3];
    const float* cprev = (const float*)d_in[4];
    const float* Wx0   = (const float*)d_in[5];
    const float* Wx1   = (const float*)d_in[6];
    const float* Wh0   = (const float*)d_in[7];
    const float* Wh1   = (const float*)d_in[8];
    const float* bx    = (const float*)d_in[9];
    const float* bh    = (const float*)d_in[10];
    float* out = (float*)d_out;

    cudaFuncSetAttribute(gemm_k, cudaFuncAttributeMaxDynamicSharedMemorySize, SMEM_TOTAL);

    // one-time host resources (no device memory involved)
    static cudaStream_t s1 = nullptr;
    static cudaEvent_t eF = nullptr, eP = nullptr, eW = nullptr,
                       eGA = nullptr, eMA = nullptr;
    static int ok = -1;
    if (ok < 0) {
        ok = 1;
        if (cudaStreamCreateWithFlags(&s1, cudaStreamNonBlocking) != cudaSuccess) ok = 0;
        if (ok && cudaEventCreateWithFlags(&eF, cudaEventDisableTiming) != cudaSuccess) ok = 0;
        if (ok && cudaEventCreateWithFlags(&eP, cudaEventDisableTiming) != cudaSuccess) ok = 0;
        if (ok && cudaEventCreateWithFlags(&eW, cudaEventDisableTiming) != cudaSuccess) ok = 0;
        if (ok && cudaEventCreateWithFlags(&eGA, cudaEventDisableTiming) != cudaSuccess) ok = 0;
        if (ok && cudaEventCreateWithFlags(&eMA, cudaEventDisableTiming) != cudaSuccess) ok = 0;
    }

    const int GA_BLOCKS = NODE_SPLIT / 8;                  // 6272
    const int GB_BLOCKS = (NPAD - NODE_SPLIT) / 8;         // 6240

    if (ok) {
        // fork s1 off stream 0
        cudaEventRecord(eF, 0);
        cudaStreamWaitEvent(s1, eF, 0);
        // branch s1: prep (for gather) then weights (for gemm)
        prep_k<<<(NNODES + 7) / 8, 256, 0, s1>>>(ei, x, hprev);
        cudaEventRecord(eP, s1);
        buildw_k<<<(512 * 512 + 255) / 256, 256, 0, s1>>>(Wx0, Wx1, Wh0, Wh1, bx, bh);
        cudaEventRecord(eW, s1);

        // stream 0: edge spine
        deg_k<<<(NEDGES / 4 + 255) / 256, 256>>>(ei, ew);
        scan1_k<<<SCAN_BLOCKS, 256>>>();
        scan2_k<<<1, 512>>>();
        fill_k<<<(NEDGES / 4 + 255) / 256, 256>>>(ei, ew);

        cudaStreamWaitEvent(0, eP, 0);                     // gather needs prep
        gather_k<<<GA_BLOCKS, 256>>>(0, x, hprev);
        cudaEventRecord(eGA, 0);
        gather_k<<<GB_BLOCKS, 256>>>(NODE_SPLIT, x, hprev);

        // branch s1: gemm_A overlaps gather_B (weights already in-stream on s1)
        cudaStreamWaitEvent(s1, eGA, 0);
        gemm_k<<<CL_SPLIT * 2, 256, SMEM_TOTAL, s1>>>(0, cprev, out);
        cudaEventRecord(eMA, s1);

        // stream 0: gemm_B after gather_B (+ weights)
        cudaStreamWaitEvent(0, eW, 0);
        gemm_k<<<(391 - CL_SPLIT) * 2, 256, SMEM_TOTAL>>>(CL_SPLIT, cprev, out);

        cudaStreamWaitEvent(0, eMA, 0);                    // join
    } else {
        // sequential fallback
        prep_k<<<(NNODES + 7) / 8, 256>>>(ei, x, hprev);
        buildw_k<<<(512 * 512 + 255) / 256, 256>>>(Wx0, Wx1, Wh0, Wh1, bx, bh);
        deg_k<<<(NEDGES / 4 + 255) / 256, 256>>>(ei, ew);
        scan1_k<<<SCAN_BLOCKS, 256>>>();
        scan2_k<<<1, 512>>>();
        fill_k<<<(NEDGES / 4 + 255) / 256, 256>>>(ei, ew);
        gather_k<<<GA_BLOCKS, 256>>>(0, x, hprev);
        gather_k<<<GB_BLOCKS, 256>>>(NODE_SPLIT, x, hprev);
        gemm_k<<<CL_SPLIT * 2, 256, SMEM_TOTAL>>>(0, cprev, out);
        gemm_k<<<(391 - CL_SPLIT) * 2, 256, SMEM_TOTAL>>>(CL_SPLIT, cprev, out);
    }
}

// round 15
// speedup vs baseline: 1.0347x; 1.0346x over previous
#include <cuda_runtime.h>
#include <cuda_bf16.h>
#include <cuda_fp16.h>
#include <math.h>
#include <stdint.h>

#define NNODES 100000
#define NEDGES 1600000
#define NPAD   100096          // 391 clusters * 256 rows
#define NCLUSTERS 391
#define SCAN_BLOCKS 391        // ceil(NNODES/256)

// Arch-specific guard: tcgen05 only exists in the sm_103a / family-specific pass.
#ifndef __CUDA_ARCH_FAMILY_SPECIFIC__
#define __CUDA_ARCH_FAMILY_SPECIFIC__ 0
#endif
#ifndef __CUDA_ARCH_SPECIFIC__
#define __CUDA_ARCH_SPECIFIC__ 0
#endif
#if defined(__CUDA_ARCH__) && (defined(__CUDA_ARCH_FEAT_SM103_ALL) || \
    (__CUDA_ARCH_FAMILY_SPECIFIC__ == 1030) || (__CUDA_ARCH_SPECIFIC__ == 1030))
#define TC_OK 1
#else
#define TC_OK 0
#endif

// ---------------- device scratch (static, no allocation) ----------------
__device__ float g_dis[NNODES];
__device__ int   g_cnt[NNODES];
__device__ int   g_loc[NNODES];
__device__ int   g_bsum[512];
__device__ int   g_cur[NNODES];
__device__ int2  g_rec[NEDGES];                      // packed {src, norm-as-int}
__device__ __half g_xh[(size_t)NNODES * 256];        // fp16 [x row | h row], 512B/node
__device__ __nv_bfloat16 g_Ah[(size_t)NPAD * 512];   // [x|Lx|h|Lh] hi
__device__ __nv_bfloat16 g_Al[(size_t)NPAD * 512];   // lo residual (x/h cols only)
__device__ __nv_bfloat16 g_Wth[512 * 512];           // W^T hi  [outcol][k]
__device__ __nv_bfloat16 g_Wtl[512 * 512];           // W^T lo
__device__ float g_bias[512];
__device__ int   g_idx64;

__device__ __forceinline__ int get_idx(const void* ei, long long pos) {
    if (g_idx64) return (int)((const long long*)ei)[pos];
    return ((const int*)ei)[pos];
}

// streaming (evict-first) 8B / 16B stores
__device__ __forceinline__ void stcs8(void* p, uint2 v) {
    unsigned long long u = (unsigned long long)v.x | ((unsigned long long)v.y << 32);
    asm volatile("st.global.cs.b64 [%0], %1;" :: "l"(p), "l"(u) : "memory");
}
__device__ __forceinline__ void stcs16(void* p, float4 v) {
    asm volatile("st.global.cs.v4.f32 [%0], {%1,%2,%3,%4};"
                 :: "l"(p), "f"(v.x), "f"(v.y), "f"(v.z), "f"(v.w) : "memory");
}

// ---------------- edge-index dtype detection (must precede deg/fill) ----------------
__global__ void detect_k(const void* ei) {
    if (threadIdx.x != 0) return;
    const unsigned long long* p = (const unsigned long long*)ei;
    int ok64 = 1;
    for (int k = 0; k < 256; k++)
        if (p[k] >= (unsigned long long)NNODES) { ok64 = 0; break; }
    g_idx64 = ok64;
}

// ---------------- bf16 hi/lo pack helpers ----------------
__device__ __forceinline__ uint2 pack_hilo(float4 v, uint2* lo) {
    __nv_bfloat16 h0 = __float2bfloat16(v.x), h1 = __float2bfloat16(v.y);
    __nv_bfloat16 h2 = __float2bfloat16(v.z), h3 = __float2bfloat16(v.w);
    __nv_bfloat16 l0 = __float2bfloat16(v.x - __bfloat162float(h0));
    __nv_bfloat16 l1 = __float2bfloat16(v.y - __bfloat162float(h1));
    __nv_bfloat16 l2 = __float2bfloat16(v.z - __bfloat162float(h2));
    __nv_bfloat16 l3 = __float2bfloat16(v.w - __bfloat162float(h3));
    uint2 ph;
    ph.x = (unsigned)__bfloat16_as_ushort(h0) | ((unsigned)__bfloat16_as_ushort(h1) << 16);
    ph.y = (unsigned)__bfloat16_as_ushort(h2) | ((unsigned)__bfloat16_as_ushort(h3) << 16);
    lo->x = (unsigned)__bfloat16_as_ushort(l0) | ((unsigned)__bfloat16_as_ushort(l1) << 16);
    lo->y = (unsigned)__bfloat16_as_ushort(l2) | ((unsigned)__bfloat16_as_ushort(l3) << 16);
    return ph;
}
__device__ __forceinline__ uint2 pack_hi_only(float4 v) {
    __nv_bfloat16 h0 = __float2bfloat16(v.x), h1 = __float2bfloat16(v.y);
    __nv_bfloat16 h2 = __float2bfloat16(v.z), h3 = __float2bfloat16(v.w);
    uint2 ph;
    ph.x = (unsigned)__bfloat16_as_ushort(h0) | ((unsigned)__bfloat16_as_ushort(h1) << 16);
    ph.y = (unsigned)__bfloat16_as_ushort(h2) | ((unsigned)__bfloat16_as_ushort(h3) << 16);
    return ph;
}

// ------- prep: zero accumulators + fp16 [x|h] packing + own-row A blocks + padding -------
__global__ void prep_k(const float* __restrict__ x, const float* __restrict__ hprev) {
    int tid = threadIdx.x;
    int i = blockIdx.x * 256 + tid;
    if (i < NNODES) { g_dis[i] = 0.f; g_cnt[i] = 0; g_cur[i] = 0; }
    int node = blockIdx.x * 8 + (tid >> 5);
    int lane = tid & 31;
    if (node >= NPAD) return;
    size_t rb = (size_t)node * 128;
    uint2* Ah2 = (uint2*)g_Ah;
    uint2* Al2 = (uint2*)g_Al;
    if (node >= NNODES) {                                 // pad rows: zeros everywhere
        uint2 z = make_uint2(0u, 0u);
        stcs8(Ah2 + rb + lane, z);        stcs8(Al2 + rb + lane, z);
        stcs8(Ah2 + rb + 32 + lane, z);
        stcs8(Ah2 + rb + 64 + lane, z);   stcs8(Al2 + rb + 64 + lane, z);
        stcs8(Ah2 + rb + 96 + lane, z);
        return;
    }
    float4 vx = ((const float4*)(x + (size_t)node * 128))[lane];
    float4 vh = ((const float4*)(hprev + (size_t)node * 128))[lane];
    // fp16 row table for the gather
    {
        __half2 x01 = __floats2half2_rn(vx.x, vx.y);
        __half2 x23 = __floats2half2_rn(vx.z, vx.w);
        __half2 h01 = __floats2half2_rn(vh.x, vh.y);
        __half2 h23 = __floats2half2_rn(vh.z, vh.w);
        uint2 px, ph;
        px.x = *(unsigned*)&x01; px.y = *(unsigned*)&x23;
        ph.x = *(unsigned*)&h01; ph.y = *(unsigned*)&h23;
        ((uint2*)g_xh)[(size_t)node * 64 + lane] = px;        // x: bytes 0..255
        ((uint2*)g_xh)[(size_t)node * 64 + 32 + lane] = ph;   // h: bytes 256..511
    }
    // own-row A blocks from exact fp32 (col4 0..31 x, 64..95 h) — hi + lo
    {
        uint2 lo, hi;
        hi = pack_hilo(vx, &lo);
        stcs8(Ah2 + rb + lane, hi);       stcs8(Al2 + rb + lane, lo);
        hi = pack_hilo(vh, &lo);
        stcs8(Ah2 + rb + 64 + lane, hi);  stcs8(Al2 + rb + 64 + lane, lo);
    }
}

// ---------------- pack W^T in bf16 hi/lo + bias ----------------
__global__ void buildw_k(const float* __restrict__ Wx0, const float* __restrict__ Wx1,
                         const float* __restrict__ Wh0, const float* __restrict__ Wh1,
                         const float* __restrict__ bx,  const float* __restrict__ bh) {
    int idx = blockIdx.x * blockDim.x + threadIdx.x;
    if (idx >= 512 * 512) return;
    int c = idx >> 9;        // k index
    int j = idx & 511;       // output col
    int g = j >> 7;
    int h = j & 127;
    int part = c >> 7;
    int cc = c & 127;
    const float* W = (part == 0) ? Wx0 : (part == 1) ? Wx1 : (part == 2) ? Wh0 : Wh1;
    float wv = W[((size_t)g * 128 + cc) * 128 + h];
    __nv_bfloat16 hi = __float2bfloat16(wv);
    float lo = wv - __bfloat162float(hi);
    g_Wth[(size_t)j * 512 + c] = hi;
    g_Wtl[(size_t)j * 512 + c] = __float2bfloat16(lo);
    if (c == 0) g_bias[j] = bx[g * 128 + h] + bh[g * 128 + h];
}

// ------- degree (sum w over src) + in-degree count (dst), 4 edges/thread -------
__global__ void deg_k(const void* __restrict__ ei, const float* __restrict__ w) {
    int e0 = (blockIdx.x * blockDim.x + threadIdx.x) * 4;
    if (e0 >= NEDGES) return;                 // NEDGES % 4 == 0
    int s[4], d[4];
    float ww[4];
#pragma unroll
    for (int i = 0; i < 4; i++) {
        s[i] = get_idx(ei, e0 + i);
        d[i] = get_idx(ei, (long long)NEDGES + e0 + i);
        ww[i] = w[e0 + i];
    }
#pragma unroll
    for (int i = 0; i < 4; i++) {
        atomicAdd(&g_dis[s[i]], ww[i]);
        atomicAdd(&g_cnt[d[i]], 1);
    }
}

// -------- scan pass 1 (per-block exclusive scan of g_cnt) + fused deg^{-1/2} --------
__global__ void scan1_k() {
    __shared__ int s[256];
    int tid = threadIdx.x;
    int i = blockIdx.x * 256 + tid;
    if (i < NNODES) {
        float d = g_dis[i];
        g_dis[i] = (d > 0.f) ? rsqrtf(d) : 0.f;
    }
    int v = (i < NNODES) ? g_cnt[i] : 0;
    s[tid] = v;
    __syncthreads();
#pragma unroll
    for (int o = 1; o < 256; o <<= 1) {
        int t = (tid >= o) ? s[tid - o] : 0;
        __syncthreads();
        s[tid] += t;
        __syncthreads();
    }
    if (i < NNODES) g_loc[i] = s[tid] - v;
    if (tid == 255) g_bsum[blockIdx.x] = s[255];
}
__global__ void scan2_k() {
    __shared__ int s[512];
    int tid = threadIdx.x;
    int v = (tid < SCAN_BLOCKS) ? g_bsum[tid] : 0;
    s[tid] = v;
    __syncthreads();
#pragma unroll
    for (int o = 1; o < 512; o <<= 1) {
        int t = (tid >= o) ? s[tid - o] : 0;
        __syncthreads();
        s[tid] += t;
        __syncthreads();
    }
    if (tid < SCAN_BLOCKS) g_bsum[tid] = s[tid] - v;
}
__device__ __forceinline__ int csr_off(int node) {
    return g_bsum[node >> 8] + g_loc[node];
}

// ------- fill packed CSR records {src, norm} grouped by dst, 4 edges/thread -------
__global__ void fill_k(const void* __restrict__ ei, const float* __restrict__ w) {
    int e0 = (blockIdx.x * blockDim.x + threadIdx.x) * 4;
    if (e0 >= NEDGES) return;
    int s[4], d[4];
    float ww[4];
#pragma unroll
    for (int i = 0; i < 4; i++) {
        s[i] = get_idx(ei, e0 + i);
        d[i] = get_idx(ei, (long long)NEDGES + e0 + i);
        ww[i] = w[e0 + i];
    }
    float dis_s[4], dis_d[4];
#pragma unroll
    for (int i = 0; i < 4; i++) { dis_s[i] = g_dis[s[i]]; dis_d[i] = g_dis[d[i]]; }
#pragma unroll
    for (int i = 0; i < 4; i++) {
        float nm = -(dis_s[i] * ww[i] * dis_d[i]);
        int pos = csr_off(d[i]) + atomicAdd(&g_cur[d[i]], 1);
        g_rec[pos] = make_int2(s[i], __float_as_int(nm));
    }
}

// ---- fp16 row accumulate: acc[0..7] += n * row8 (one uint4 = 8 fp16) ----
__device__ __forceinline__ void acc8(float* acc, uint4 v, float n) {
    float2 f;
    f = __half22float2(*(__half2*)&v.x); acc[0] += n * f.x; acc[1] += n * f.y;
    f = __half22float2(*(__half2*)&v.y); acc[2] += n * f.x; acc[3] += n * f.y;
    f = __half22float2(*(__half2*)&v.z); acc[4] += n * f.x; acc[5] += n * f.y;
    f = __half22float2(*(__half2*)&v.w); acc[6] += n * f.x; acc[7] += n * f.y;
}

// ---- pull-gather on fp16 [x|h] rows (512B/edge): L-blocks only (hi) ----
__global__ __launch_bounds__(256) void gather_k() {
    int node = blockIdx.x * 8 + (threadIdx.x >> 5);
    int lane = threadIdx.x & 31;
    if (node >= NNODES) return;
    size_t rb = (size_t)node * 128;                       // row base in uint2 units
    uint2* Ah2 = (uint2*)g_Ah;
    int p = csr_off(node);
    int end = (node + 1 < NNODES) ? csr_off(node + 1) : NEDGES;

    const uint4* rows = (const uint4*)g_xh;
    float acc[8];
#pragma unroll
    for (int k = 0; k < 8; k++) acc[k] = 0.f;

    for (; p + 3 < end; p += 4) {
        int2 r0 = g_rec[p],     r1 = g_rec[p + 1];
        int2 r2 = g_rec[p + 2], r3 = g_rec[p + 3];
        uint4 v0 = __ldg(rows + (size_t)r0.x * 32 + lane);
        uint4 v1 = __ldg(rows + (size_t)r1.x * 32 + lane);
        uint4 v2 = __ldg(rows + (size_t)r2.x * 32 + lane);
        uint4 v3 = __ldg(rows + (size_t)r3.x * 32 + lane);
        acc8(acc, v0, __int_as_float(r0.y));
        acc8(acc, v1, __int_as_float(r1.y));
        acc8(acc, v2, __int_as_float(r2.y));
        acc8(acc, v3, __int_as_float(r3.y));
    }
    for (; p < end; p++) {
        int2 r0 = g_rec[p];
        uint4 v0 = __ldg(rows + (size_t)r0.x * 32 + lane);
        acc8(acc, v0, __int_as_float(r0.y));
    }

    // L-block hi-only write: lanes 0..15 -> Lx (col4 32..63), 16..31 -> Lh (96..127)
    int l2 = (lane < 16) ? (32 + 2 * lane) : (96 + 2 * (lane - 16));
    uint2 hi0 = pack_hi_only(make_float4(acc[0], acc[1], acc[2], acc[3]));
    uint2 hi1 = pack_hi_only(make_float4(acc[4], acc[5], acc[6], acc[7]));
    stcs8(Ah2 + rb + l2, hi0);
    stcs8(Ah2 + rb + l2 + 1, hi1);
}

// ======= cta_group::2 tcgen05 bf16x3 GEMM (pass-interleaved) + LSTM epilogue =======
#define STAGE_BYTES 98304
#define SMEM_DATA0  1024
#define SMEM_TOTAL  (SMEM_DATA0 + 2 * STAGE_BYTES)     // 197632
#define NK_TILES    8
#define AL_TILE(t)  (((t) & 2) == 0)                   // t in {0,1,4,5}

__device__ __forceinline__ float sigmoidf_(float v) { return 1.f / (1.f + expf(-v)); }

#if TC_OK
static __device__ __forceinline__ unsigned swz(unsigned off) {
    return off ^ ((off >> 3) & 0x70);
}
static __device__ __forceinline__ void cp16(uint32_t s, const void* g) {
    asm volatile("cp.async.cg.shared.global [%0], [%1], 16;" :: "r"(s), "l"(g));
}
static __device__ __forceinline__ void mbar_wait(uint32_t mbar, uint32_t parity) {
    asm volatile(
        "{\n\t.reg .pred P;\n"
        "W%=:\n\t"
        "mbarrier.try_wait.parity.acquire.cluster.shared::cta.b64 P, [%0], %1, 0x989680;\n\t"
        "@P bra D%=;\n\t"
        "bra W%=;\n"
        "D%=:\n\t}"
        :: "r"(mbar), "r"(parity) : "memory");
}
// idesc cg2 kind::f16: dtype=F32, a/b=BF16, N=256, M=256
#define IDESC_CG2 0x10400490u
#define DESC_BASE ((2ull << 61) | (1ull << 46) | (64ull << 32) | (1ull << 16))
#define MKDESC(a) (DESC_BASE | (((a) >> 4) & 0x3FFF))

static __device__ __forceinline__ void mma_cg2(uint32_t d, uint64_t ad, uint64_t bd, bool en) {
    uint32_t e = en ? 1u : 0u;
    asm volatile(
        "{\n\t.reg .pred p;\n\t"
        "setp.ne.u32 p, %4, 0;\n\t"
        "tcgen05.mma.cta_group::2.kind::f16 [%0], %1, %2, %3, {%5,%5,%5,%5,%5,%5,%5,%5}, p;\n\t}"
        :: "r"(d), "l"(ad), "l"(bd), "r"(IDESC_CG2), "r"(e), "r"(0u) : "memory");
}

static __device__ __forceinline__ void load_tile(uint32_t sbase, int t, int stage,
                                                 int cbase, int rank, int tid) {
    int k0 = t << 6;
    uint32_t sb = sbase + SMEM_DATA0 + stage * STAGE_BYTES;
#pragma unroll
    for (int b = 0; b < 4; b++) {             // B halves: Bh_n0, Bh_n1, Bl_n0, Bl_n1
        const __nv_bfloat16* src = (b < 2) ? g_Wth : g_Wtl;
        int rowbase = ((b & 1) << 8) + rank * 128;
#pragma unroll
        for (int i = 0; i < 4; i++) {
            int q = tid + (i << 8);
            int row = q >> 3, c = q & 7;
            unsigned off = (row << 7) + (c << 4);
            cp16(sb + b * 16384 + swz(off),
                 src + (size_t)(rowbase + row) * 512 + k0 + c * 8);
        }
    }
    {                                         // A-hi: own 128 M-rows
#pragma unroll
        for (int i = 0; i < 4; i++) {
            int q = tid + (i << 8);
            int row = q >> 3, c = q & 7;
            unsigned off = (row << 7) + (c << 4);
            cp16(sb + 65536 + swz(off),
                 g_Ah + (size_t)(cbase + rank * 128 + row) * 512 + k0 + c * 8);
        }
    }
    if (AL_TILE(t)) {                         // A-lo only on x/h tiles
#pragma unroll
        for (int i = 0; i < 4; i++) {
            int q = tid + (i << 8);
            int row = q >> 3, c = q & 7;
            unsigned off = (row << 7) + (c << 4);
            cp16(sb + 81920 + swz(off),
                 g_Al + (size_t)(cbase + rank * 128 + row) * 512 + k0 + c * 8);
        }
    }
    asm volatile("cp.async.commit_group;" ::: "memory");
}
#endif  // TC_OK

__global__ __launch_bounds__(256, 1) __cluster_dims__(2, 1, 1)
void gemm_k(const float* __restrict__ cprev, float* __restrict__ out) {
#if TC_OK
    extern __shared__ __align__(1024) char smem[];
    uint32_t sbase;
    asm("{ .reg .u64 t; cvta.to.shared.u64 t, %1; cvt.u32.u64 %0, t; }"
        : "=r"(sbase) : "l"(smem));
    const int tid = threadIdx.x;
    uint32_t rank;
    asm("mov.u32 %0, %%cluster_ctarank;" : "=r"(rank));
    const int cbase = (blockIdx.x >> 1) << 8;            // cluster row base (256 rows)
    const uint32_t ready = sbase + 8;                    // leader's: count=2
    const uint32_t done  = sbase + 16;                   // per-CTA: count=1 (multicast commit)

    if (tid < 32) {
        asm volatile("tcgen05.alloc.cta_group::2.sync.aligned.shared::cta.b32 [%0], %1;"
                     :: "r"(sbase), "r"(512) : "memory");
        asm volatile("tcgen05.relinquish_alloc_permit.cta_group::2.sync.aligned;");
    }
    if (tid == 0) {
        asm volatile("mbarrier.init.shared.b64 [%0], %1;" :: "r"(ready), "r"(2) : "memory");
        asm volatile("mbarrier.init.shared.b64 [%0], %1;" :: "r"(done), "r"(1) : "memory");
    }
    __syncthreads();
    asm volatile("barrier.cluster.arrive.aligned;" ::: "memory");
    asm volatile("barrier.cluster.wait.aligned;" ::: "memory");

    uint32_t tmem;
    asm("ld.shared.b32 %0, [%1];" : "=r"(tmem) : "r"(sbase));

    load_tile(sbase, 0, 0, cbase, rank, tid);
    for (int t = 0; t < NK_TILES; t++) {
        if (t + 1 < NK_TILES) {
            if (t >= 1) mbar_wait(done, (t - 1) & 1);    // stage (t+1)&1 free
            load_tile(sbase, t + 1, (t + 1) & 1, cbase, rank, tid);
        }
        if (t + 1 < NK_TILES)
            asm volatile("cp.async.wait_group 1;" ::: "memory");
        else
            asm volatile("cp.async.wait_group 0;" ::: "memory");
        asm volatile("fence.proxy.async.shared::cta;" ::: "memory");
        __syncthreads();
        if (tid == 0) {
            asm volatile(
                "{\n\t.reg .b32 r;\n\t"
                "mapa.shared::cluster.u32 r, %0, 0;\n\t"
                "mbarrier.arrive.shared::cluster.b64 _, [r];\n\t}"
                :: "r"(ready) : "memory");
            if (rank == 0) {
                mbar_wait(ready, t & 1);                 // both CTAs' tiles ready
                uint32_t st = sbase + SMEM_DATA0 + (t & 1) * STAGE_BYTES;
                uint64_t bh0 = MKDESC(st);
                uint64_t bh1 = MKDESC(st + 16384);
                uint64_t bl0 = MKDESC(st + 32768);
                uint64_t bl1 = MKDESC(st + 49152);
                uint64_t ah  = MKDESC(st + 65536);
                uint64_t al  = MKDESC(st + 81920);
                const bool do_al = AL_TILE(t);
#pragma unroll
                for (int ks = 0; ks < 4; ks++) {
                    bool acc = !(t == 0 && ks == 0);
                    uint64_t o = ks * 2;
                    mma_cg2(tmem,       ah + o, bh0 + o, acc);
                    mma_cg2(tmem + 256, ah + o, bh1 + o, acc);
                    mma_cg2(tmem,       ah + o, bl0 + o, true);
                    mma_cg2(tmem + 256, ah + o, bl1 + o, true);
                    if (do_al) {
                        mma_cg2(tmem,       al + o, bh0 + o, true);
                        mma_cg2(tmem + 256, al + o, bh1 + o, true);
                    }
                }
                asm volatile(
                    "tcgen05.commit.cta_group::2.mbarrier::arrive::one.shared::cluster.multicast::cluster.b64 [%0], %1;"
                    :: "r"(done), "h"((uint16_t)0x3) : "memory");
            }
        }
    }
    mbar_wait(done, 0);                                  // tile 6
    mbar_wait(done, 1);                                  // tile 7
    asm volatile("tcgen05.fence::after_thread_sync;" ::: "memory");
    __syncthreads();

    // ---- fused LSTM epilogue: 8 warps, direct streaming float4 stores ----
    {
        const int row = tid & 127;
        const int colbase = (tid >> 7) << 6;             // 0 or 64
        const int grow = cbase + (int)rank * 128 + row;
        const bool ok = grow < NNODES;
        float* oh = out + (size_t)grow * 128;
        float* oc = oh + (size_t)NNODES * 128;
        const float4* cp4base = (const float4*)(cprev + (size_t)grow * 128);

#pragma unroll 1
        for (int ch = 0; ch < 4; ch++) {
            const int c0 = colbase + ch * 16;
            uint32_t ri[16], rf[16], rg[16], ro[16];
            #define LD16(arr, addr) \
                asm volatile("tcgen05.ld.sync.aligned.32x32b.x16.b32 " \
                    "{%0,%1,%2,%3,%4,%5,%6,%7,%8,%9,%10,%11,%12,%13,%14,%15}, [%16];" \
                    : "=r"(arr[0]),"=r"(arr[1]),"=r"(arr[2]),"=r"(arr[3]), \
                      "=r"(arr[4]),"=r"(arr[5]),"=r"(arr[6]),"=r"(arr[7]), \
                      "=r"(arr[8]),"=r"(arr[9]),"=r"(arr[10]),"=r"(arr[11]), \
                      "=r"(arr[12]),"=r"(arr[13]),"=r"(arr[14]),"=r"(arr[15]) \
                    : "r"(addr))
            LD16(ri, tmem +   0 + c0);
            LD16(rf, tmem + 128 + c0);
            LD16(rg, tmem + 256 + c0);
            LD16(ro, tmem + 384 + c0);
            #undef LD16
            asm volatile("tcgen05.wait::ld.sync.aligned;" ::: "memory");

            float cpv[16];
            if (ok) {
#pragma unroll
                for (int q = 0; q < 4; q++)
                    *(float4*)&cpv[q * 4] = cp4base[(c0 >> 2) + q];
            } else {
#pragma unroll
                for (int q = 0; q < 16; q++) cpv[q] = 0.f;
            }

            float hv[16], cv[16];
#pragma unroll
            for (int j = 0; j < 16; j++) {
                int col = c0 + j;
                float gi = __uint_as_float(ri[j]) + g_bias[col];
                float gf = __uint_as_float(rf[j]) + g_bias[128 + col];
                float gg = __uint_as_float(rg[j]) + g_bias[256 + col];
                float go = __uint_as_float(ro[j]) + g_bias[384 + col];
                float c = sigmoidf_(gf) * cpv[j] + sigmoidf_(gi) * tanhf(gg);
                cv[j] = c;
                hv[j] = sigmoidf_(go) * tanhf(c);
            }
            if (ok) {
#pragma unroll
                for (int j = 0; j < 16; j += 4) {
                    stcs16(oh + c0 + j, make_float4(hv[j], hv[j+1], hv[j+2], hv[j+3]));
                    stcs16(oc + c0 + j, make_float4(cv[j], cv[j+1], cv[j+2], cv[j+3]));
                }
            }
        }
        asm volatile("tcgen05.fence::before_thread_sync;" ::: "memory");
    }
    __syncthreads();
    if (tid < 32) {
        asm volatile("tcgen05.dealloc.cta_group::2.sync.aligned.b32 %0, %1;"
                     :: "r"(tmem), "r"(512));
    }
    asm volatile("barrier.cluster.arrive.aligned;" ::: "memory");
    asm volatile("barrier.cluster.wait.aligned;" ::: "memory");

#else  // !TC_OK — correct scalar fallback for the non-sm_103a pass (never run).
    const int tid = threadIdx.x;
    const int bm = blockIdx.x * 128;
    for (int idx = tid; idx < 128 * 128; idx += 256) {
        int row = idx >> 7, col = idx & 127;
        int grow = bm + row;
        if (grow >= NNODES) continue;
        float acc0 = g_bias[col], acc1 = g_bias[128 + col];
        float acc2 = g_bias[256 + col], acc3 = g_bias[384 + col];
        for (int k = 0; k < 512; k++) {
            int part = k >> 7;
            float al = (part == 0 || part == 2)
                       ? __bfloat162float(g_Al[(size_t)grow * 512 + k]) : 0.f;
            float a = __bfloat162float(g_Ah[(size_t)grow * 512 + k]) + al;
            acc0 += a * (__bfloat162float(g_Wth[(size_t)(0 * 128 + col) * 512 + k]) +
                         __bfloat162float(g_Wtl[(size_t)(0 * 128 + col) * 512 + k]));
            acc1 += a * (__bfloat162float(g_Wth[(size_t)(1 * 128 + col) * 512 + k]) +
                         __bfloat162float(g_Wtl[(size_t)(1 * 128 + col) * 512 + k]));
            acc2 += a * (__bfloat162float(g_Wth[(size_t)(2 * 128 + col) * 512 + k]) +
                         __bfloat162float(g_Wtl[(size_t)(2 * 128 + col) * 512 + k]));
            acc3 += a * (__bfloat162float(g_Wth[(size_t)(3 * 128 + col) * 512 + k]) +
                         __bfloat162float(g_Wtl[(size_t)(3 * 128 + col) * 512 + k]));
        }
        float c = sigmoidf_(acc1) * cprev[(size_t)grow * 128 + col] +
                  sigmoidf_(acc0) * tanhf(acc2);
        out[(size_t)grow * 128 + col] = sigmoidf_(acc3) * tanhf(c);
        out[(size_t)NNODES * 128 + (size_t)grow * 128 + col] = c;
    }
#endif  // TC_OK
}

// ---------------- launch: detect -> fork {prep, buildw} || {deg..fill} -> gather -> gemm ----------------
extern "C" void kernel_launch(void* const* d_in, const int* in_sizes, int n_in,
                              void* d_out, int out_size) {
    const float* x     = (const float*)d_in[0];
    const void*  ei    = d_in[1];
    const float* ew    = (const float*)d_in[2];
    const float* hprev = (const float*)d_in[3];
    const float* cprev = (const float*)d_in[4];
    const float* Wx0   = (const float*)d_in[5];
    const float* Wx1   = (const float*)d_in[6];
    const float* Wh0   = (const float*)d_in[7];
    const float* Wh1   = (const float*)d_in[8];
    const float* bx    = (const float*)d_in[9];
    const float* bh    = (const float*)d_in[10];
    float* out = (float*)d_out;

    cudaFuncSetAttribute(gemm_k, cudaFuncAttributeMaxDynamicSharedMemorySize, SMEM_TOTAL);

    static cudaStream_t s1 = nullptr;
    static cudaEvent_t eF = nullptr, eP = nullptr, eW = nullptr;
    static int ok = -1;
    if (ok < 0) {
        ok = 1;
        if (cudaStreamCreateWithFlags(&s1, cudaStreamNonBlocking) != cudaSuccess) ok = 0;
        if (ok && cudaEventCreateWithFlags(&eF, cudaEventDisableTiming) != cudaSuccess) ok = 0;
        if (ok && cudaEventCreateWithFlags(&eP, cudaEventDisableTiming) != cudaSuccess) ok = 0;
        if (ok && cudaEventCreateWithFlags(&eW, cudaEventDisableTiming) != cudaSuccess) ok = 0;
    }

    if (ok) {
        detect_k<<<1, 32>>>(ei);                          // settles g_idx64 before the fork
        cudaEventRecord(eF, 0);
        cudaStreamWaitEvent(s1, eF, 0);

        // branch s1: node-side prep (A own-rows + fp16 table + zeroing), then weights
        prep_k<<<(NPAD + 7) / 8, 256, 0, s1>>>(x, hprev);
        cudaEventRecord(eP, s1);
        buildw_k<<<(512 * 512 + 255) / 256, 256, 0, s1>>>(Wx0, Wx1, Wh0, Wh1, bx, bh);
        cudaEventRecord(eW, s1);

        // stream 0: edge spine (needs g_dis/g_cnt zeroed by prep -> wait eP before deg)
        cudaStreamWaitEvent(0, eP, 0);
        deg_k<<<(NEDGES / 4 + 255) / 256, 256>>>(ei, ew);
        scan1_k<<<SCAN_BLOCKS, 256>>>();
        scan2_k<<<1, 512>>>();
        fill_k<<<(NEDGES / 4 + 255) / 256, 256>>>(ei, ew);

        gather_k<<<(NNODES + 7) / 8, 256>>>();
        cudaStreamWaitEvent(0, eW, 0);                    // gemm needs weights
        gemm_k<<<NCLUSTERS * 2, 256, SMEM_TOTAL>>>(cprev, out);
    } else {
        detect_k<<<1, 32>>>(ei);
        prep_k<<<(NPAD + 7) / 8, 256>>>(x, hprev);
        buildw_k<<<(512 * 512 + 255) / 256, 256>>>(Wx0, Wx1, Wh0, Wh1, bx, bh);
        deg_k<<<(NEDGES / 4 + 255) / 256, 256>>>(ei, ew);
        scan1_k<<<SCAN_BLOCKS, 256>>>();
        scan2_k<<<1, 512>>>();
        fill_k<<<(NEDGES / 4 + 255) / 256, 256>>>(ei, ew);
        gather_k<<<(NNODES + 7) / 8, 256>>>();
        gemm_k<<<NCLUSTERS * 2, 256, SMEM_TOTAL>>>(cprev, out);
    }
}

// round 16
// speedup vs baseline: 1.1744x; 1.1350x over previous
#include <cuda_runtime.h>
#include <cuda_bf16.h>
#include <cuda_fp16.h>
#include <math.h>
#include <stdint.h>

#define NNODES 100000
#define NEDGES 1600000
#define NPAD   100096          // 391 clusters * 256 rows
#define NCLUSTERS 391
#define SCAN_BLOCKS 391        // ceil(NNODES/256)

// Arch-specific guard: tcgen05 only exists in the sm_103a / family-specific pass.
#ifndef __CUDA_ARCH_FAMILY_SPECIFIC__
#define __CUDA_ARCH_FAMILY_SPECIFIC__ 0
#endif
#ifndef __CUDA_ARCH_SPECIFIC__
#define __CUDA_ARCH_SPECIFIC__ 0
#endif
#if defined(__CUDA_ARCH__) && (defined(__CUDA_ARCH_FEAT_SM103_ALL) || \
    (__CUDA_ARCH_FAMILY_SPECIFIC__ == 1030) || (__CUDA_ARCH_SPECIFIC__ == 1030))
#define TC_OK 1
#else
#define TC_OK 0
#endif

// ---------------- device scratch (static, no allocation) ----------------
__device__ float g_dis[NNODES];
__device__ int   g_cnt[NNODES];
__device__ int   g_loc[NNODES];
__device__ int   g_bsum[512];
__device__ int   g_cur[NNODES];
__device__ int2  g_rec[NEDGES];                      // packed {src, norm-as-int}
__device__ __half g_xh[(size_t)NNODES * 256];        // fp16 [x row | h row], 512B/node
__device__ __nv_bfloat16 g_Ah[(size_t)NPAD * 512];   // [x|Lx|h|Lh] hi
__device__ __nv_bfloat16 g_Al[(size_t)NPAD * 512];   // lo residual (x/h cols only)
__device__ __nv_bfloat16 g_Wth[512 * 512];           // W^T hi  [outcol][k]
__device__ __nv_bfloat16 g_Wtl[512 * 512];           // W^T lo
__device__ float g_bias[512];
__device__ int   g_idx64;

__device__ __forceinline__ int get_idx(const void* ei, long long pos) {
    if (g_idx64) return (int)((const long long*)ei)[pos];
    return ((const int*)ei)[pos];
}

// streaming (evict-first) 8B / 16B stores
__device__ __forceinline__ void stcs8(void* p, uint2 v) {
    unsigned long long u = (unsigned long long)v.x | ((unsigned long long)v.y << 32);
    asm volatile("st.global.cs.b64 [%0], %1;" :: "l"(p), "l"(u) : "memory");
}
__device__ __forceinline__ void stcs16(void* p, float4 v) {
    asm volatile("st.global.cs.v4.f32 [%0], {%1,%2,%3,%4};"
                 :: "l"(p), "f"(v.x), "f"(v.y), "f"(v.z), "f"(v.w) : "memory");
}

// ---------------- edge-index dtype detection (must precede deg/fill) ----------------
__global__ void detect_k(const void* ei) {
    if (threadIdx.x != 0) return;
    const unsigned long long* p = (const unsigned long long*)ei;
    int ok64 = 1;
    for (int k = 0; k < 256; k++)
        if (p[k] >= (unsigned long long)NNODES) { ok64 = 0; break; }
    g_idx64 = ok64;
}

// ---------------- bf16 hi/lo pack helpers ----------------
__device__ __forceinline__ uint2 pack_hilo(float4 v, uint2* lo) {
    __nv_bfloat16 h0 = __float2bfloat16(v.x), h1 = __float2bfloat16(v.y);
    __nv_bfloat16 h2 = __float2bfloat16(v.z), h3 = __float2bfloat16(v.w);
    __nv_bfloat16 l0 = __float2bfloat16(v.x - __bfloat162float(h0));
    __nv_bfloat16 l1 = __float2bfloat16(v.y - __bfloat162float(h1));
    __nv_bfloat16 l2 = __float2bfloat16(v.z - __bfloat162float(h2));
    __nv_bfloat16 l3 = __float2bfloat16(v.w - __bfloat162float(h3));
    uint2 ph;
    ph.x = (unsigned)__bfloat16_as_ushort(h0) | ((unsigned)__bfloat16_as_ushort(h1) << 16);
    ph.y = (unsigned)__bfloat16_as_ushort(h2) | ((unsigned)__bfloat16_as_ushort(h3) << 16);
    lo->x = (unsigned)__bfloat16_as_ushort(l0) | ((unsigned)__bfloat16_as_ushort(l1) << 16);
    lo->y = (unsigned)__bfloat16_as_ushort(l2) | ((unsigned)__bfloat16_as_ushort(l3) << 16);
    return ph;
}
__device__ __forceinline__ uint2 pack_hi_only(float4 v) {
    __nv_bfloat16 h0 = __float2bfloat16(v.x), h1 = __float2bfloat16(v.y);
    __nv_bfloat16 h2 = __float2bfloat16(v.z), h3 = __float2bfloat16(v.w);
    uint2 ph;
    ph.x = (unsigned)__bfloat16_as_ushort(h0) | ((unsigned)__bfloat16_as_ushort(h1) << 16);
    ph.y = (unsigned)__bfloat16_as_ushort(h2) | ((unsigned)__bfloat16_as_ushort(h3) << 16);
    return ph;
}

// ------- prep: zero accumulators + fp16 [x|h] packing + own-row A blocks + padding -------
__global__ void prep_k(const float* __restrict__ x, const float* __restrict__ hprev) {
    int tid = threadIdx.x;
    int i = blockIdx.x * 256 + tid;
    if (i < NNODES) { g_dis[i] = 0.f; g_cnt[i] = 0; g_cur[i] = 0; }
    int node = blockIdx.x * 8 + (tid >> 5);
    int lane = tid & 31;
    if (node >= NPAD) return;
    size_t rb = (size_t)node * 128;
    uint2* Ah2 = (uint2*)g_Ah;
    uint2* Al2 = (uint2*)g_Al;
    if (node >= NNODES) {                                 // pad rows: zeros everywhere
        uint2 z = make_uint2(0u, 0u);
        stcs8(Ah2 + rb + lane, z);        stcs8(Al2 + rb + lane, z);
        stcs8(Ah2 + rb + 32 + lane, z);
        stcs8(Ah2 + rb + 64 + lane, z);   stcs8(Al2 + rb + 64 + lane, z);
        stcs8(Ah2 + rb + 96 + lane, z);
        return;
    }
    float4 vx = ((const float4*)(x + (size_t)node * 128))[lane];
    float4 vh = ((const float4*)(hprev + (size_t)node * 128))[lane];
    {
        __half2 x01 = __floats2half2_rn(vx.x, vx.y);
        __half2 x23 = __floats2half2_rn(vx.z, vx.w);
        __half2 h01 = __floats2half2_rn(vh.x, vh.y);
        __half2 h23 = __floats2half2_rn(vh.z, vh.w);
        uint2 px, ph;
        px.x = *(unsigned*)&x01; px.y = *(unsigned*)&x23;
        ph.x = *(unsigned*)&h01; ph.y = *(unsigned*)&h23;
        ((uint2*)g_xh)[(size_t)node * 64 + lane] = px;        // x: bytes 0..255
        ((uint2*)g_xh)[(size_t)node * 64 + 32 + lane] = ph;   // h: bytes 256..511
    }
    {
        uint2 lo, hi;
        hi = pack_hilo(vx, &lo);
        stcs8(Ah2 + rb + lane, hi);       stcs8(Al2 + rb + lane, lo);
        hi = pack_hilo(vh, &lo);
        stcs8(Ah2 + rb + 64 + lane, hi);  stcs8(Al2 + rb + 64 + lane, lo);
    }
}

// ---------------- pack W^T in bf16 hi/lo + bias ----------------
__global__ void buildw_k(const float* __restrict__ Wx0, const float* __restrict__ Wx1,
                         const float* __restrict__ Wh0, const float* __restrict__ Wh1,
                         const float* __restrict__ bx,  const float* __restrict__ bh) {
    int idx = blockIdx.x * blockDim.x + threadIdx.x;
    if (idx >= 512 * 512) return;
    int c = idx >> 9;        // k index
    int j = idx & 511;       // output col
    int g = j >> 7;
    int h = j & 127;
    int part = c >> 7;
    int cc = c & 127;
    const float* W = (part == 0) ? Wx0 : (part == 1) ? Wx1 : (part == 2) ? Wh0 : Wh1;
    float wv = W[((size_t)g * 128 + cc) * 128 + h];
    __nv_bfloat16 hi = __float2bfloat16(wv);
    float lo = wv - __bfloat162float(hi);
    g_Wth[(size_t)j * 512 + c] = hi;
    g_Wtl[(size_t)j * 512 + c] = __float2bfloat16(lo);
    if (c == 0) g_bias[j] = bx[g * 128 + h] + bh[g * 128 + h];
}

// ------- degree (sum w over src) + in-degree count (dst), 4 edges/thread -------
__global__ void deg_k(const void* __restrict__ ei, const float* __restrict__ w) {
    int e0 = (blockIdx.x * blockDim.x + threadIdx.x) * 4;
    if (e0 >= NEDGES) return;                 // NEDGES % 4 == 0
    int s[4], d[4];
    float ww[4];
#pragma unroll
    for (int i = 0; i < 4; i++) {
        s[i] = get_idx(ei, e0 + i);
        d[i] = get_idx(ei, (long long)NEDGES + e0 + i);
        ww[i] = w[e0 + i];
    }
#pragma unroll
    for (int i = 0; i < 4; i++) {
        atomicAdd(&g_dis[s[i]], ww[i]);
        atomicAdd(&g_cnt[d[i]], 1);
    }
}

// -------- scan pass 1 (per-block exclusive scan of g_cnt) + fused deg^{-1/2} --------
__global__ void scan1_k() {
    __shared__ int s[256];
    int tid = threadIdx.x;
    int i = blockIdx.x * 256 + tid;
    if (i < NNODES) {
        float d = g_dis[i];
        g_dis[i] = (d > 0.f) ? rsqrtf(d) : 0.f;
    }
    int v = (i < NNODES) ? g_cnt[i] : 0;
    s[tid] = v;
    __syncthreads();
#pragma unroll
    for (int o = 1; o < 256; o <<= 1) {
        int t = (tid >= o) ? s[tid - o] : 0;
        __syncthreads();
        s[tid] += t;
        __syncthreads();
    }
    if (i < NNODES) g_loc[i] = s[tid] - v;
    if (tid == 255) g_bsum[blockIdx.x] = s[255];
}
__global__ void scan2_k() {
    __shared__ int s[512];
    int tid = threadIdx.x;
    int v = (tid < SCAN_BLOCKS) ? g_bsum[tid] : 0;
    s[tid] = v;
    __syncthreads();
#pragma unroll
    for (int o = 1; o < 512; o <<= 1) {
        int t = (tid >= o) ? s[tid - o] : 0;
        __syncthreads();
        s[tid] += t;
        __syncthreads();
    }
    if (tid < SCAN_BLOCKS) g_bsum[tid] = s[tid] - v;
}
__device__ __forceinline__ int csr_off(int node) {
    return g_bsum[node >> 8] + g_loc[node];
}

// ------- fill packed CSR records {src, norm} grouped by dst, 4 edges/thread -------
__global__ void fill_k(const void* __restrict__ ei, const float* __restrict__ w) {
    int e0 = (blockIdx.x * blockDim.x + threadIdx.x) * 4;
    if (e0 >= NEDGES) return;
    int s[4], d[4];
    float ww[4];
#pragma unroll
    for (int i = 0; i < 4; i++) {
        s[i] = get_idx(ei, e0 + i);
        d[i] = get_idx(ei, (long long)NEDGES + e0 + i);
        ww[i] = w[e0 + i];
    }
    float dis_s[4], dis_d[4];
#pragma unroll
    for (int i = 0; i < 4; i++) { dis_s[i] = g_dis[s[i]]; dis_d[i] = g_dis[d[i]]; }
#pragma unroll
    for (int i = 0; i < 4; i++) {
        float nm = -(dis_s[i] * ww[i] * dis_d[i]);
        int pos = csr_off(d[i]) + atomicAdd(&g_cur[d[i]], 1);
        g_rec[pos] = make_int2(s[i], __float_as_int(nm));
    }
}

// ---- fp16 row accumulate: acc[0..7] += n * row8 (one uint4 = 8 fp16) ----
__device__ __forceinline__ void acc8(float* acc, uint4 v, float n) {
    float2 f;
    f = __half22float2(*(__half2*)&v.x); acc[0] += n * f.x; acc[1] += n * f.y;
    f = __half22float2(*(__half2*)&v.y); acc[2] += n * f.x; acc[3] += n * f.y;
    f = __half22float2(*(__half2*)&v.z); acc[4] += n * f.x; acc[5] += n * f.y;
    f = __half22float2(*(__half2*)&v.w); acc[6] += n * f.x; acc[7] += n * f.y;
}

// ---- pull-gather on fp16 [x|h] rows (512B/edge): L-blocks only (hi) ----
__global__ __launch_bounds__(256) void gather_k() {
    int node = blockIdx.x * 8 + (threadIdx.x >> 5);
    int lane = threadIdx.x & 31;
    if (node >= NNODES) return;
    size_t rb = (size_t)node * 128;                       // row base in uint2 units
    uint2* Ah2 = (uint2*)g_Ah;
    int p = csr_off(node);
    int end = (node + 1 < NNODES) ? csr_off(node + 1) : NEDGES;

    const uint4* rows = (const uint4*)g_xh;
    float acc[8];
#pragma unroll
    for (int k = 0; k < 8; k++) acc[k] = 0.f;

    for (; p + 3 < end; p += 4) {
        int2 r0 = g_rec[p],     r1 = g_rec[p + 1];
        int2 r2 = g_rec[p + 2], r3 = g_rec[p + 3];
        uint4 v0 = __ldg(rows + (size_t)r0.x * 32 + lane);
        uint4 v1 = __ldg(rows + (size_t)r1.x * 32 + lane);
        uint4 v2 = __ldg(rows + (size_t)r2.x * 32 + lane);
        uint4 v3 = __ldg(rows + (size_t)r3.x * 32 + lane);
        acc8(acc, v0, __int_as_float(r0.y));
        acc8(acc, v1, __int_as_float(r1.y));
        acc8(acc, v2, __int_as_float(r2.y));
        acc8(acc, v3, __int_as_float(r3.y));
    }
    for (; p < end; p++) {
        int2 r0 = g_rec[p];
        uint4 v0 = __ldg(rows + (size_t)r0.x * 32 + lane);
        acc8(acc, v0, __int_as_float(r0.y));
    }

    int l2 = (lane < 16) ? (32 + 2 * lane) : (96 + 2 * (lane - 16));
    uint2 hi0 = pack_hi_only(make_float4(acc[0], acc[1], acc[2], acc[3]));
    uint2 hi1 = pack_hi_only(make_float4(acc[4], acc[5], acc[6], acc[7]));
    stcs8(Ah2 + rb + l2, hi0);
    stcs8(Ah2 + rb + l2 + 1, hi1);
}

// ======= cta_group::2 tcgen05 bf16x3 GEMM (pass-interleaved) + LSTM epilogue =======
#define STAGE_BYTES 98304
#define SMEM_DATA0  1024
#define SMEM_TOTAL  (SMEM_DATA0 + 2 * STAGE_BYTES)     // 197632
#define NK_TILES    8
#define AL_TILE(t)  (((t) & 2) == 0)                   // t in {0,1,4,5}

// Fast transcendentals: __expf (MUFU.EX2 path, rel err ~2^-21) + approx divide.
// Error contribution ~1e-6 abs — invisible vs the 3.5e-4 bf16/fp16 budget.
__device__ __forceinline__ float sigmoidf_(float v) {
    return __fdividef(1.f, 1.f + __expf(-v));
}
__device__ __forceinline__ float tanhf_(float v) {
    return __fdividef(2.f, 1.f + __expf(-2.f * v)) - 1.f;
}

#if TC_OK
static __device__ __forceinline__ unsigned swz(unsigned off) {
    return off ^ ((off >> 3) & 0x70);
}
static __device__ __forceinline__ void cp16(uint32_t s, const void* g) {
    asm volatile("cp.async.cg.shared.global [%0], [%1], 16;" :: "r"(s), "l"(g));
}
static __device__ __forceinline__ void mbar_wait(uint32_t mbar, uint32_t parity) {
    asm volatile(
        "{\n\t.reg .pred P;\n"
        "W%=:\n\t"
        "mbarrier.try_wait.parity.acquire.cluster.shared::cta.b64 P, [%0], %1, 0x989680;\n\t"
        "@P bra D%=;\n\t"
        "bra W%=;\n"
        "D%=:\n\t}"
        :: "r"(mbar), "r"(parity) : "memory");
}
// idesc cg2 kind::f16: dtype=F32, a/b=BF16, N=256, M=256
#define IDESC_CG2 0x10400490u
#define DESC_BASE ((2ull << 61) | (1ull << 46) | (64ull << 32) | (1ull << 16))
#define MKDESC(a) (DESC_BASE | (((a) >> 4) & 0x3FFF))

static __device__ __forceinline__ void mma_cg2(uint32_t d, uint64_t ad, uint64_t bd, bool en) {
    uint32_t e = en ? 1u : 0u;
    asm volatile(
        "{\n\t.reg .pred p;\n\t"
        "setp.ne.u32 p, %4, 0;\n\t"
        "tcgen05.mma.cta_group::2.kind::f16 [%0], %1, %2, %3, {%5,%5,%5,%5,%5,%5,%5,%5}, p;\n\t}"
        :: "r"(d), "l"(ad), "l"(bd), "r"(IDESC_CG2), "r"(e), "r"(0u) : "memory");
}

static __device__ __forceinline__ void load_tile(uint32_t sbase, int t, int stage,
                                                 int cbase, int rank, int tid) {
    int k0 = t << 6;
    uint32_t sb = sbase + SMEM_DATA0 + stage * STAGE_BYTES;
#pragma unroll
    for (int b = 0; b < 4; b++) {             // B halves: Bh_n0, Bh_n1, Bl_n0, Bl_n1
        const __nv_bfloat16* src = (b < 2) ? g_Wth : g_Wtl;
        int rowbase = ((b & 1) << 8) + rank * 128;
#pragma unroll
        for (int i = 0; i < 4; i++) {
            int q = tid + (i << 8);
            int row = q >> 3, c = q & 7;
            unsigned off = (row << 7) + (c << 4);
            cp16(sb + b * 16384 + swz(off),
                 src + (size_t)(rowbase + row) * 512 + k0 + c * 8);
        }
    }
    {                                         // A-hi: own 128 M-rows
#pragma unroll
        for (int i = 0; i < 4; i++) {
            int q = tid + (i << 8);
            int row = q >> 3, c = q & 7;
            unsigned off = (row << 7) + (c << 4);
            cp16(sb + 65536 + swz(off),
                 g_Ah + (size_t)(cbase + rank * 128 + row) * 512 + k0 + c * 8);
        }
    }
    if (AL_TILE(t)) {                         // A-lo only on x/h tiles
#pragma unroll
        for (int i = 0; i < 4; i++) {
            int q = tid + (i << 8);
            int row = q >> 3, c = q & 7;
            unsigned off = (row << 7) + (c << 4);
            cp16(sb + 81920 + swz(off),
                 g_Al + (size_t)(cbase + rank * 128 + row) * 512 + k0 + c * 8);
        }
    }
    asm volatile("cp.async.commit_group;" ::: "memory");
}
#endif  // TC_OK

__global__ __launch_bounds__(256, 1) __cluster_dims__(2, 1, 1)
void gemm_k(const float* __restrict__ cprev, float* __restrict__ out) {
#if TC_OK
    extern __shared__ __align__(1024) char smem[];
    uint32_t sbase;
    asm("{ .reg .u64 t; cvta.to.shared.u64 t, %1; cvt.u32.u64 %0, t; }"
        : "=r"(sbase) : "l"(smem));
    const int tid = threadIdx.x;
    uint32_t rank;
    asm("mov.u32 %0, %%cluster_ctarank;" : "=r"(rank));
    const int cbase = (blockIdx.x >> 1) << 8;            // cluster row base (256 rows)
    const uint32_t ready = sbase + 8;                    // leader's: count=2
    const uint32_t done  = sbase + 16;                   // per-CTA: count=1 (multicast commit)

    if (tid < 32) {
        asm volatile("tcgen05.alloc.cta_group::2.sync.aligned.shared::cta.b32 [%0], %1;"
                     :: "r"(sbase), "r"(512) : "memory");
        asm volatile("tcgen05.relinquish_alloc_permit.cta_group::2.sync.aligned;");
    }
    if (tid == 0) {
        asm volatile("mbarrier.init.shared.b64 [%0], %1;" :: "r"(ready), "r"(2) : "memory");
        asm volatile("mbarrier.init.shared.b64 [%0], %1;" :: "r"(done), "r"(1) : "memory");
    }
    __syncthreads();
    asm volatile("barrier.cluster.arrive.aligned;" ::: "memory");
    asm volatile("barrier.cluster.wait.aligned;" ::: "memory");

    uint32_t tmem;
    asm("ld.shared.b32 %0, [%1];" : "=r"(tmem) : "r"(sbase));

    load_tile(sbase, 0, 0, cbase, rank, tid);
    for (int t = 0; t < NK_TILES; t++) {
        if (t + 1 < NK_TILES) {
            if (t >= 1) mbar_wait(done, (t - 1) & 1);    // stage (t+1)&1 free
            load_tile(sbase, t + 1, (t + 1) & 1, cbase, rank, tid);
        }
        if (t + 1 < NK_TILES)
            asm volatile("cp.async.wait_group 1;" ::: "memory");
        else
            asm volatile("cp.async.wait_group 0;" ::: "memory");
        asm volatile("fence.proxy.async.shared::cta;" ::: "memory");
        __syncthreads();
        if (tid == 0) {
            asm volatile(
                "{\n\t.reg .b32 r;\n\t"
                "mapa.shared::cluster.u32 r, %0, 0;\n\t"
                "mbarrier.arrive.shared::cluster.b64 _, [r];\n\t}"
                :: "r"(ready) : "memory");
            if (rank == 0) {
                mbar_wait(ready, t & 1);                 // both CTAs' tiles ready
                uint32_t st = sbase + SMEM_DATA0 + (t & 1) * STAGE_BYTES;
                uint64_t bh0 = MKDESC(st);
                uint64_t bh1 = MKDESC(st + 16384);
                uint64_t bl0 = MKDESC(st + 32768);
                uint64_t bl1 = MKDESC(st + 49152);
                uint64_t ah  = MKDESC(st + 65536);
                uint64_t al  = MKDESC(st + 81920);
                const bool do_al = AL_TILE(t);
#pragma unroll
                for (int ks = 0; ks < 4; ks++) {
                    bool acc = !(t == 0 && ks == 0);
                    uint64_t o = ks * 2;
                    mma_cg2(tmem,       ah + o, bh0 + o, acc);
                    mma_cg2(tmem + 256, ah + o, bh1 + o, acc);
                    mma_cg2(tmem,       ah + o, bl0 + o, true);
                    mma_cg2(tmem + 256, ah + o, bl1 + o, true);
                    if (do_al) {
                        mma_cg2(tmem,       al + o, bh0 + o, true);
                        mma_cg2(tmem + 256, al + o, bh1 + o, true);
                    }
                }
                asm volatile(
                    "tcgen05.commit.cta_group::2.mbarrier::arrive::one.shared::cluster.multicast::cluster.b64 [%0], %1;"
                    :: "r"(done), "h"((uint16_t)0x3) : "memory");
            }
        }
    }
    mbar_wait(done, 0);                                  // tile 6
    mbar_wait(done, 1);                                  // tile 7
    asm volatile("tcgen05.fence::after_thread_sync;" ::: "memory");
    __syncthreads();

    // ---- fused LSTM epilogue: 8 warps, fast-math activations, streaming stores ----
    {
        const int row = tid & 127;
        const int colbase = (tid >> 7) << 6;             // 0 or 64
        const int grow = cbase + (int)rank * 128 + row;
        const bool ok = grow < NNODES;
        float* oh = out + (size_t)grow * 128;
        float* oc = oh + (size_t)NNODES * 128;
        const float4* cp4base = (const float4*)(cprev + (size_t)grow * 128);

#pragma unroll 1
        for (int ch = 0; ch < 4; ch++) {
            const int c0 = colbase + ch * 16;
            uint32_t ri[16], rf[16], rg[16], ro[16];
            #define LD16(arr, addr) \
                asm volatile("tcgen05.ld.sync.aligned.32x32b.x16.b32 " \
                    "{%0,%1,%2,%3,%4,%5,%6,%7,%8,%9,%10,%11,%12,%13,%14,%15}, [%16];" \
                    : "=r"(arr[0]),"=r"(arr[1]),"=r"(arr[2]),"=r"(arr[3]), \
                      "=r"(arr[4]),"=r"(arr[5]),"=r"(arr[6]),"=r"(arr[7]), \
                      "=r"(arr[8]),"=r"(arr[9]),"=r"(arr[10]),"=r"(arr[11]), \
                      "=r"(arr[12]),"=r"(arr[13]),"=r"(arr[14]),"=r"(arr[15]) \
                    : "r"(addr))
            LD16(ri, tmem +   0 + c0);
            LD16(rf, tmem + 128 + c0);
            LD16(rg, tmem + 256 + c0);
            LD16(ro, tmem + 384 + c0);
            #undef LD16
            asm volatile("tcgen05.wait::ld.sync.aligned;" ::: "memory");

            float cpv[16];
            if (ok) {
#pragma unroll
                for (int q = 0; q < 4; q++)
                    *(float4*)&cpv[q * 4] = cp4base[(c0 >> 2) + q];
            } else {
#pragma unroll
                for (int q = 0; q < 16; q++) cpv[q] = 0.f;
            }

            float hv[16], cv[16];
#pragma unroll
            for (int j = 0; j < 16; j++) {
                int col = c0 + j;
                float gi = __uint_as_float(ri[j]) + g_bias[col];
                float gf = __uint_as_float(rf[j]) + g_bias[128 + col];
                float gg = __uint_as_float(rg[j]) + g_bias[256 + col];
                float go = __uint_as_float(ro[j]) + g_bias[384 + col];
                float c = sigmoidf_(gf) * cpv[j] + sigmoidf_(gi) * tanhf_(gg);
                cv[j] = c;
                hv[j] = sigmoidf_(go) * tanhf_(c);
            }
            if (ok) {
#pragma unroll
                for (int j = 0; j < 16; j += 4) {
                    stcs16(oh + c0 + j, make_float4(hv[j], hv[j+1], hv[j+2], hv[j+3]));
                    stcs16(oc + c0 + j, make_float4(cv[j], cv[j+1], cv[j+2], cv[j+3]));
                }
            }
        }
        asm volatile("tcgen05.fence::before_thread_sync;" ::: "memory");
    }
    __syncthreads();
    if (tid < 32) {
        asm volatile("tcgen05.dealloc.cta_group::2.sync.aligned.b32 %0, %1;"
                     :: "r"(tmem), "r"(512));
    }
    asm volatile("barrier.cluster.arrive.aligned;" ::: "memory");
    asm volatile("barrier.cluster.wait.aligned;" ::: "memory");

#else  // !TC_OK — correct scalar fallback for the non-sm_103a pass (never run).
    const int tid = threadIdx.x;
    const int bm = blockIdx.x * 128;
    for (int idx = tid; idx < 128 * 128; idx += 256) {
        int row = idx >> 7, col = idx & 127;
        int grow = bm + row;
        if (grow >= NNODES) continue;
        float acc0 = g_bias[col], acc1 = g_bias[128 + col];
        float acc2 = g_bias[256 + col], acc3 = g_bias[384 + col];
        for (int k = 0; k < 512; k++) {
            int part = k >> 7;
            float al = (part == 0 || part == 2)
                       ? __bfloat162float(g_Al[(size_t)grow * 512 + k]) : 0.f;
            float a = __bfloat162float(g_Ah[(size_t)grow * 512 + k]) + al;
            acc0 += a * (__bfloat162float(g_Wth[(size_t)(0 * 128 + col) * 512 + k]) +
                         __bfloat162float(g_Wtl[(size_t)(0 * 128 + col) * 512 + k]));
            acc1 += a * (__bfloat162float(g_Wth[(size_t)(1 * 128 + col) * 512 + k]) +
                         __bfloat162float(g_Wtl[(size_t)(1 * 128 + col) * 512 + k]));
            acc2 += a * (__bfloat162float(g_Wth[(size_t)(2 * 128 + col) * 512 + k]) +
                         __bfloat162float(g_Wtl[(size_t)(2 * 128 + col) * 512 + k]));
            acc3 += a * (__bfloat162float(g_Wth[(size_t)(3 * 128 + col) * 512 + k]) +
                         __bfloat162float(g_Wtl[(size_t)(3 * 128 + col) * 512 + k]));
        }
        float c = sigmoidf_(acc1) * cprev[(size_t)grow * 128 + col] +
                  sigmoidf_(acc0) * tanhf_(acc2);
        out[(size_t)grow * 128 + col] = sigmoidf_(acc3) * tanhf_(c);
        out[(size_t)NNODES * 128 + (size_t)grow * 128 + col] = c;
    }
#endif  // TC_OK
}

// ---------------- launch: detect -> fork {prep, buildw} || {deg..fill} -> gather -> gemm ----------------
extern "C" void kernel_launch(void* const* d_in, const int* in_sizes, int n_in,
                              void* d_out, int out_size) {
    const float* x     = (const float*)d_in[0];
    const void*  ei    = d_in[1];
    const float* ew    = (const float*)d_in[2];
    const float* hprev = (const float*)d_in[3];
    const float* cprev = (const float*)d_in[4];
    const float* Wx0   = (const float*)d_in[5];
    const float* Wx1   = (const float*)d_in[6];
    const float* Wh0   = (const float*)d_in[7];
    const float* Wh1   = (const float*)d_in[8];
    const float* bx    = (const float*)d_in[9];
    const float* bh    = (const float*)d_in[10];
    float* out = (float*)d_out;

    cudaFuncSetAttribute(gemm_k, cudaFuncAttributeMaxDynamicSharedMemorySize, SMEM_TOTAL);

    static cudaStream_t s1 = nullptr;
    static cudaEvent_t eF = nullptr, eP = nullptr, eW = nullptr;
    static int ok = -1;
    if (ok < 0) {
        ok = 1;
        if (cudaStreamCreateWithFlags(&s1, cudaStreamNonBlocking) != cudaSuccess) ok = 0;
        if (ok && cudaEventCreateWithFlags(&eF, cudaEventDisableTiming) != cudaSuccess) ok = 0;
        if (ok && cudaEventCreateWithFlags(&eP, cudaEventDisableTiming) != cudaSuccess) ok = 0;
        if (ok && cudaEventCreateWithFlags(&eW, cudaEventDisableTiming) != cudaSuccess) ok = 0;
    }

    if (ok) {
        detect_k<<<1, 32>>>(ei);                          // settles g_idx64 before the fork
        cudaEventRecord(eF, 0);
        cudaStreamWaitEvent(s1, eF, 0);

        prep_k<<<(NPAD + 7) / 8, 256, 0, s1>>>(x, hprev);
        cudaEventRecord(eP, s1);
        buildw_k<<<(512 * 512 + 255) / 256, 256, 0, s1>>>(Wx0, Wx1, Wh0, Wh1, bx, bh);
        cudaEventRecord(eW, s1);

        cudaStreamWaitEvent(0, eP, 0);
        deg_k<<<(NEDGES / 4 + 255) / 256, 256>>>(ei, ew);
        scan1_k<<<SCAN_BLOCKS, 256>>>();
        scan2_k<<<1, 512>>>();
        fill_k<<<(NEDGES / 4 + 255) / 256, 256>>>(ei, ew);

        gather_k<<<(NNODES + 7) / 8, 256>>>();
        cudaStreamWaitEvent(0, eW, 0);
        gemm_k<<<NCLUSTERS * 2, 256, SMEM_TOTAL>>>(cprev, out);
    } else {
        detect_k<<<1, 32>>>(ei);
        prep_k<<<(NPAD + 7) / 8, 256>>>(x, hprev);
        buildw_k<<<(512 * 512 + 255) / 256, 256>>>(Wx0, Wx1, Wh0, Wh1, bx, bh);
        deg_k<<<(NEDGES / 4 + 255) / 256, 256>>>(ei, ew);
        scan1_k<<<SCAN_BLOCKS, 256>>>();
        scan2_k<<<1, 512>>>();
        fill_k<<<(NEDGES / 4 + 255) / 256, 256>>>(ei, ew);
        gather_k<<<(NNODES + 7) / 8, 256>>>();
        gemm_k<<<NCLUSTERS * 2, 256, SMEM_TOTAL>>>(cprev, out);
    }
}